// round 2
// baseline (speedup 1.0000x reference)
#include <cuda_runtime.h>
#include <cuda_bf16.h>
#include <math.h>

// ---------------- problem constants ----------------
#define BB     2
#define SS     2048
#define NDIM   2048
#define NH     16
#define QRANK  1536
#define KVRANK 512
#define ROPE_D 64
#define NOPE_D 128
#define VDIM   128
#define QKH    192           // NOPE + ROPE
#define ROWS   (BB*SS)       // 4096
#define KVDIM  (NH*(NOPE_D+VDIM))  // 4096
#define QDIM   (NH*QKH)      // 3072
#define CDIM   (KVRANK+ROPE_D) // 576

// ---------------- scratch (device globals; no allocs allowed) ----------------
__device__ float g_cq  [ROWS*QRANK];   // 25 MB
__device__ float g_q   [ROWS*QDIM];    // 50 MB
__device__ float g_c   [ROWS*CDIM];    // 9.4 MB
__device__ float g_kvn [ROWS*KVRANK];  // 8.4 MB
__device__ float g_kv  [ROWS*KVDIM];   // 67 MB
__device__ float g_attn[ROWS*(NH*VDIM)]; // 33 MB

// ---------------- generic SGEMM: C[M,N] = A[M,K] * B[N,K]^T ----------------
// tile 128(M) x 64(N) x 16(K), 256 threads, 8x4 microtile.
#define GM 128
#define GN 64
#define GK 16

__global__ __launch_bounds__(256) void sgemm_nt(
    const float* __restrict__ A, const float* __restrict__ B,
    float* __restrict__ C, int M, int N, int K)
{
    __shared__ float As[GK][GM+4];   // pad -> ~2-way store conflicts only
    __shared__ float Bs[GK][GN+4];

    const int tid = threadIdx.x;
    const int tx  = tid & 15;        // N direction, 4 cols each
    const int ty  = tid >> 4;        // M direction, 8 rows each
    const int m0  = blockIdx.y * GM;
    const int n0  = blockIdx.x * GN;

    const int lc = tid & 15;         // k within tile
    const int lr = tid >> 4;         // row stripe

    const float* Ap = A + (size_t)(m0 + lr) * K + lc;
    const float* Bp = B + (size_t)(n0 + lr) * K + lc;

    float acc[8][4];
    #pragma unroll
    for (int i = 0; i < 8; i++)
        #pragma unroll
        for (int j = 0; j < 4; j++) acc[i][j] = 0.f;

    for (int k0 = 0; k0 < K; k0 += GK) {
        #pragma unroll
        for (int i = 0; i < 8; i++)
            As[lc][lr + 16*i] = Ap[(size_t)(16*i) * K + k0];
        #pragma unroll
        for (int i = 0; i < 4; i++)
            Bs[lc][lr + 16*i] = Bp[(size_t)(16*i) * K + k0];
        __syncthreads();

        #pragma unroll
        for (int kk = 0; kk < GK; kk++) {
            float4 a0 = *(const float4*)&As[kk][ty*8];
            float4 a1 = *(const float4*)&As[kk][ty*8 + 4];
            float4 b0 = *(const float4*)&Bs[kk][tx*4];
            float av[8] = {a0.x,a0.y,a0.z,a0.w,a1.x,a1.y,a1.z,a1.w};
            float bv[4] = {b0.x,b0.y,b0.z,b0.w};
            #pragma unroll
            for (int i = 0; i < 8; i++)
                #pragma unroll
                for (int j = 0; j < 4; j++)
                    acc[i][j] = fmaf(av[i], bv[j], acc[i][j]);
        }
        __syncthreads();
    }

    #pragma unroll
    for (int i = 0; i < 8; i++) {
        size_t row = (size_t)(m0 + ty*8 + i);
        float4 o = make_float4(acc[i][0], acc[i][1], acc[i][2], acc[i][3]);
        *(float4*)&C[row * N + n0 + tx*4] = o;
    }
}

// ---------------- RMSNorm: out[row, :L] = in[row, :L] * rsqrt(mean(x^2)+eps) * w ----------------
__global__ __launch_bounds__(256) void rmsnorm_k(
    const float* __restrict__ in, float* __restrict__ out,
    const float* __restrict__ w, int L, int sin, int sout)
{
    __shared__ float red[8];
    const int row = blockIdx.x;
    const float* ip = in + (size_t)row * sin;
    float ss = 0.f;
    for (int i = threadIdx.x; i < L; i += 256) {
        float v = ip[i];
        ss = fmaf(v, v, ss);
    }
    #pragma unroll
    for (int off = 16; off; off >>= 1)
        ss += __shfl_xor_sync(0xffffffffu, ss, off);
    if ((threadIdx.x & 31) == 0) red[threadIdx.x >> 5] = ss;
    __syncthreads();
    if (threadIdx.x == 0) {
        float tot = 0.f;
        #pragma unroll
        for (int i = 0; i < 8; i++) tot += red[i];
        red[0] = rsqrtf(tot / (float)L + 1e-6f);
    }
    __syncthreads();
    float inv = red[0];
    for (int i = threadIdx.x; i < L; i += 256)
        out[(size_t)row * sout + i] = ip[i] * inv * w[i];
}

// ---------------- RoPE ----------------
// q layout: g_q[row, h*192 + 128 + 2p {,+1}] ; freqs_cis: [S, 32, 2] (cos, sin)
__global__ void rope_q(float* __restrict__ q, const float* __restrict__ fc)
{
    int idx = blockIdx.x * blockDim.x + threadIdx.x;
    if (idx >= ROWS * NH * 32) return;
    int p = idx & 31;
    int h = (idx >> 5) & 15;
    int r = idx >> 9;
    int s = r & (SS - 1);
    float cs = fc[(s*32 + p)*2 + 0];
    float sn = fc[(s*32 + p)*2 + 1];
    float* base = q + (size_t)r * QDIM + h * QKH + NOPE_D + 2*p;
    float xr = base[0], xi = base[1];
    base[0] = xr*cs - xi*sn;
    base[1] = xr*sn + xi*cs;
}

__global__ void rope_k(float* __restrict__ c, const float* __restrict__ fc)
{
    int idx = blockIdx.x * blockDim.x + threadIdx.x;
    if (idx >= ROWS * 32) return;
    int p = idx & 31;
    int r = idx >> 5;
    int s = r & (SS - 1);
    float cs = fc[(s*32 + p)*2 + 0];
    float sn = fc[(s*32 + p)*2 + 1];
    float* base = c + (size_t)r * CDIM + KVRANK + 2*p;
    float xr = base[0], xi = base[1];
    base[0] = xr*cs - xi*sn;
    base[1] = xr*sn + xi*cs;
}

// ---------------- Flash attention (causal, online softmax) ----------------
// q tile 64 rows x d=192; k tile 32 x 192 (stored TRANSPOSED in smem, pad stride 34
// to avoid 16-way bank conflicts), v tile 32 x 128.
// 256 threads: ty=tid/16 owns 4 q-rows, tx=tid%16 owns 2 score-cols / 8 out-cols.
#define FAM 64
#define FAN 32
#define FAD 192
#define FAV 128
#define KTS 34   // transposed-K row stride (floats), even for float2 alignment

#define FA_SMEM_FLOATS (FAM*FAD + FAD*KTS + FAN*FAV + FAM*FAN + 2*FAM)

__global__ __launch_bounds__(256) void flash_attn(
    const float* __restrict__ gq, const float* __restrict__ gkv,
    const float* __restrict__ gc, float* __restrict__ gout)
{
    extern __shared__ float sm[];
    float* Qs = sm;                  // [64][192]
    float* KT = Qs + FAM*FAD;        // [192][34] transposed K
    float* Vs = KT + FAD*KTS;        // [32][128]
    float* Ps = Vs + FAN*FAV;        // [64][32]
    float* Ms = Ps + FAM*FAN;        // [64]
    float* Ls = Ms + FAM;            // [64]

    const int tid = threadIdx.x;
    const int tx = tid & 15, ty = tid >> 4;
    const int q0 = blockIdx.x * FAM;
    const int h  = blockIdx.y;
    const int b  = blockIdx.z;
    const int rb = b * SS;

    // load Q tile (qf = [nope | roped pe] is contiguous per head in g_q)
    const float* qp = gq + (size_t)(rb + q0) * QDIM + h * QKH;
    for (int i = tid; i < FAM*FAD; i += 256) {
        int r = i / FAD, c = i - r * FAD;
        Qs[i] = qp[(size_t)r * QDIM + c];
    }
    if (tid < FAM) { Ms[tid] = -INFINITY; Ls[tid] = 0.f; }

    float acc[4][8];
    #pragma unroll
    for (int i = 0; i < 4; i++)
        #pragma unroll
        for (int j = 0; j < 8; j++) acc[i][j] = 0.f;
    __syncthreads();

    const float scale = 0.07216878364870323f; // 1/sqrt(192)
    const int kend = q0 + FAM;

    for (int n0 = 0; n0 < kend; n0 += FAN) {
        // K tile, transposed: KT[c*34 + j] = kf[n0+j][c]
        for (int i = tid; i < FAN*FAD; i += 256) {
            int j = i / FAD, c = i - j * FAD;
            size_t row = (size_t)(rb + n0 + j);
            float v = (c < NOPE_D)
                ? gkv[row * KVDIM + h*256 + c]
                : gc [row * CDIM  + KVRANK + (c - NOPE_D)];
            KT[c * KTS + j] = v;
        }
        // V tile
        for (int i = tid; i < FAN*FAV; i += 256) {
            int j = i >> 7, c = i & 127;
            Vs[i] = gkv[(size_t)(rb + n0 + j) * KVDIM + h*256 + NOPE_D + c];
        }
        __syncthreads();

        // scores: S[4 rows][2 cols] per thread
        float sc0[4] = {0,0,0,0}, sc1[4] = {0,0,0,0};
        for (int kk = 0; kk < FAD; kk += 4) {
            float qv[4][4];
            #pragma unroll
            for (int i = 0; i < 4; i++) {
                float4 t4 = *(const float4*)&Qs[(ty*4 + i) * FAD + kk];
                qv[i][0]=t4.x; qv[i][1]=t4.y; qv[i][2]=t4.z; qv[i][3]=t4.w;
            }
            #pragma unroll
            for (int u = 0; u < 4; u++) {
                float2 k2 = *(const float2*)&KT[(kk + u) * KTS + tx*2];
                #pragma unroll
                for (int i = 0; i < 4; i++) {
                    sc0[i] = fmaf(qv[i][u], k2.x, sc0[i]);
                    sc1[i] = fmaf(qv[i][u], k2.y, sc1[i]);
                }
            }
        }

        // online softmax update (rows owned per-warp: warp w owns rows 8w..8w+7)
        #pragma unroll
        for (int i = 0; i < 4; i++) {
            int row = ty*4 + i;
            int qi = q0 + row;
            int kj = n0 + tx*2;
            float s0 = (kj     <= qi) ? sc0[i]*scale : -INFINITY;
            float s1 = (kj + 1 <= qi) ? sc1[i]*scale : -INFINITY;
            float rm = fmaxf(s0, s1);
            #pragma unroll
            for (int off = 8; off; off >>= 1)
                rm = fmaxf(rm, __shfl_xor_sync(0xffffffffu, rm, off));
            float mold = Ms[row];
            float mnew = fmaxf(mold, rm);
            float p0 = __expf(s0 - mnew);
            float p1 = __expf(s1 - mnew);
            float rs = p0 + p1;
            #pragma unroll
            for (int off = 8; off; off >>= 1)
                rs += __shfl_xor_sync(0xffffffffu, rs, off);
            float alpha = __expf(mold - mnew);
            float lnew = Ls[row] * alpha + rs;
            if (tx == 0) { Ms[row] = mnew; Ls[row] = lnew; }
            *(float2*)&Ps[row * FAN + tx*2] = make_float2(p0, p1);
            #pragma unroll
            for (int c = 0; c < 8; c++) acc[i][c] *= alpha;
        }
        __syncthreads();

        // O += P @ V  (thread: 4 rows x 8 v-cols)
        for (int j = 0; j < FAN; j++) {
            float4 v0 = *(const float4*)&Vs[j * FAV + tx*8];
            float4 v1 = *(const float4*)&Vs[j * FAV + tx*8 + 4];
            #pragma unroll
            for (int i = 0; i < 4; i++) {
                float p = Ps[(ty*4 + i) * FAN + j];
                acc[i][0] = fmaf(p, v0.x, acc[i][0]);
                acc[i][1] = fmaf(p, v0.y, acc[i][1]);
                acc[i][2] = fmaf(p, v0.z, acc[i][2]);
                acc[i][3] = fmaf(p, v0.w, acc[i][3]);
                acc[i][4] = fmaf(p, v1.x, acc[i][4]);
                acc[i][5] = fmaf(p, v1.y, acc[i][5]);
                acc[i][6] = fmaf(p, v1.z, acc[i][6]);
                acc[i][7] = fmaf(p, v1.w, acc[i][7]);
            }
        }
        __syncthreads();
    }

    // finalize: O /= l, write to g_attn[row, h*128 + c]
    #pragma unroll
    for (int i = 0; i < 4; i++) {
        int row = ty*4 + i;
        float inv = 1.f / Ls[row];
        float* op = gout + (size_t)(rb + q0 + row) * (NH*VDIM) + h*VDIM + tx*8;
        *(float4*)op       = make_float4(acc[i][0]*inv, acc[i][1]*inv, acc[i][2]*inv, acc[i][3]*inv);
        *(float4*)(op + 4) = make_float4(acc[i][4]*inv, acc[i][5]*inv, acc[i][6]*inv, acc[i][7]*inv);
    }
}

// ---------------- launcher ----------------
extern "C" void kernel_launch(void* const* d_in, const int* in_sizes, int n_in,
                              void* d_out, int out_size)
{
    const float* x     = (const float*)d_in[0];
    const float* fc    = (const float*)d_in[1];
    const float* wq_a  = (const float*)d_in[2];
    const float* qnw   = (const float*)d_in[3];
    const float* wq_b  = (const float*)d_in[4];
    const float* wkv_a = (const float*)d_in[5];
    const float* kvnw  = (const float*)d_in[6];
    const float* wkv_b = (const float*)d_in[7];
    const float* wo    = (const float*)d_in[8];
    float* out = (float*)d_out;

    float *cq, *q, *c, *kvn, *kv, *attn;
    cudaGetSymbolAddress((void**)&cq,   g_cq);
    cudaGetSymbolAddress((void**)&q,    g_q);
    cudaGetSymbolAddress((void**)&c,    g_c);
    cudaGetSymbolAddress((void**)&kvn,  g_kvn);
    cudaGetSymbolAddress((void**)&kv,   g_kv);
    cudaGetSymbolAddress((void**)&attn, g_attn);

    // 1) cq = x @ wq_a^T               [4096,1536]
    sgemm_nt<<<dim3(QRANK/GN, ROWS/GM), 256>>>(x, wq_a, cq, ROWS, QRANK, NDIM);
    // 2) rmsnorm(cq) in place
    rmsnorm_k<<<ROWS, 256>>>(cq, cq, qnw, QRANK, QRANK, QRANK);
    // 3) q = cqn @ wq_b^T              [4096,3072]
    sgemm_nt<<<dim3(QDIM/GN, ROWS/GM), 256>>>(cq, wq_b, q, ROWS, QDIM, QRANK);
    // 4) c = x @ wkv_a^T               [4096,576]
    sgemm_nt<<<dim3(CDIM/GN, ROWS/GM), 256>>>(x, wkv_a, c, ROWS, CDIM, NDIM);
    // 5) kvn = rmsnorm(c[:, :512])
    rmsnorm_k<<<ROWS, 256>>>(c, kvn, kvnw, KVRANK, CDIM, KVRANK);
    // 6) kv = kvn @ wkv_b^T            [4096,4096]
    sgemm_nt<<<dim3(KVDIM/GN, ROWS/GM), 256>>>(kvn, wkv_b, kv, ROWS, KVDIM, KVRANK);
    // 7) RoPE on q_pe (in g_q) and k_pe (in g_c)
    rope_q<<<(ROWS*NH*32 + 255)/256, 256>>>(q, fc);
    rope_k<<<(ROWS*32   + 255)/256, 256>>>(c, fc);
    // 8) flash attention -> g_attn     [4096, 2048]
    const int fa_bytes = FA_SMEM_FLOATS * (int)sizeof(float);
    cudaFuncSetAttribute(flash_attn, cudaFuncAttributeMaxDynamicSharedMemorySize, fa_bytes);
    flash_attn<<<dim3(SS/FAM, NH, BB), 256, fa_bytes>>>(q, kv, c, attn);
    // 9) out = attn @ wo^T             [4096, 2048]
    sgemm_nt<<<dim3(NDIM/GN, ROWS/GM), 256>>>(attn, wo, out, ROWS, NDIM, NH*VDIM);
}

// round 3
// speedup vs baseline: 1.0032x; 1.0032x over previous
#include <cuda_runtime.h>
#include <cuda_bf16.h>
#include <math.h>

// ---------------- problem constants ----------------
#define BB     2
#define SS     2048
#define NDIM   2048
#define NH     16
#define QRANK  1536
#define KVRANK 512
#define ROPE_D 64
#define NOPE_D 128
#define VDIM   128
#define QKH    192           // NOPE + ROPE
#define ROWS   (BB*SS)       // 4096
#define KVDIM  (NH*(NOPE_D+VDIM))  // 4096
#define QDIM   (NH*QKH)      // 3072
#define CDIM   (KVRANK+ROPE_D) // 576

// ---------------- scratch (device globals; no allocs allowed) ----------------
__device__ float g_cq  [ROWS*QRANK];   // 25 MB
__device__ float g_q   [ROWS*QDIM];    // 50 MB
__device__ float g_c   [ROWS*CDIM];    // 9.4 MB
__device__ float g_kvn [ROWS*KVRANK];  // 8.4 MB
__device__ float g_kv  [ROWS*KVDIM];   // 67 MB
__device__ float g_attn[ROWS*(NH*VDIM)]; // 33 MB

// ---------------- generic SGEMM: C[M,N] = A[M,K] * B[N,K]^T ----------------
// tile 128(M) x 64(N) x 16(K), 256 threads, 8x4 microtile.
#define GM 128
#define GN 64
#define GK 16

__global__ __launch_bounds__(256) void sgemm_nt(
    const float* __restrict__ A, const float* __restrict__ B,
    float* __restrict__ C, int M, int N, int K)
{
    __shared__ float As[GK][GM+4];   // pad -> ~2-way store conflicts only
    __shared__ float Bs[GK][GN+4];

    const int tid = threadIdx.x;
    const int tx  = tid & 15;        // N direction, 4 cols each
    const int ty  = tid >> 4;        // M direction, 8 rows each
    const int m0  = blockIdx.y * GM;
    const int n0  = blockIdx.x * GN;

    const int lc = tid & 15;         // k within tile
    const int lr = tid >> 4;         // row stripe

    const float* Ap = A + (size_t)(m0 + lr) * K + lc;
    const float* Bp = B + (size_t)(n0 + lr) * K + lc;

    float acc[8][4];
    #pragma unroll
    for (int i = 0; i < 8; i++)
        #pragma unroll
        for (int j = 0; j < 4; j++) acc[i][j] = 0.f;

    for (int k0 = 0; k0 < K; k0 += GK) {
        #pragma unroll
        for (int i = 0; i < 8; i++)
            As[lc][lr + 16*i] = Ap[(size_t)(16*i) * K + k0];
        #pragma unroll
        for (int i = 0; i < 4; i++)
            Bs[lc][lr + 16*i] = Bp[(size_t)(16*i) * K + k0];
        __syncthreads();

        #pragma unroll
        for (int kk = 0; kk < GK; kk++) {
            float4 a0 = *(const float4*)&As[kk][ty*8];
            float4 a1 = *(const float4*)&As[kk][ty*8 + 4];
            float4 b0 = *(const float4*)&Bs[kk][tx*4];
            float av[8] = {a0.x,a0.y,a0.z,a0.w,a1.x,a1.y,a1.z,a1.w};
            float bv[4] = {b0.x,b0.y,b0.z,b0.w};
            #pragma unroll
            for (int i = 0; i < 8; i++)
                #pragma unroll
                for (int j = 0; j < 4; j++)
                    acc[i][j] = fmaf(av[i], bv[j], acc[i][j]);
        }
        __syncthreads();
    }

    #pragma unroll
    for (int i = 0; i < 8; i++) {
        size_t row = (size_t)(m0 + ty*8 + i);
        float4 o = make_float4(acc[i][0], acc[i][1], acc[i][2], acc[i][3]);
        *(float4*)&C[row * N + n0 + tx*4] = o;
    }
}

// ---------------- RMSNorm: out[row, :L] = in[row, :L] * rsqrt(mean(x^2)+eps) * w ----------------
__global__ __launch_bounds__(256) void rmsnorm_k(
    const float* __restrict__ in, float* __restrict__ out,
    const float* __restrict__ w, int L, int sin, int sout)
{
    __shared__ float red[8];
    const int row = blockIdx.x;
    const float* ip = in + (size_t)row * sin;
    float ss = 0.f;
    for (int i = threadIdx.x; i < L; i += 256) {
        float v = ip[i];
        ss = fmaf(v, v, ss);
    }
    #pragma unroll
    for (int off = 16; off; off >>= 1)
        ss += __shfl_xor_sync(0xffffffffu, ss, off);
    if ((threadIdx.x & 31) == 0) red[threadIdx.x >> 5] = ss;
    __syncthreads();
    if (threadIdx.x == 0) {
        float tot = 0.f;
        #pragma unroll
        for (int i = 0; i < 8; i++) tot += red[i];
        red[0] = rsqrtf(tot / (float)L + 1e-6f);
    }
    __syncthreads();
    float inv = red[0];
    for (int i = threadIdx.x; i < L; i += 256)
        out[(size_t)row * sout + i] = ip[i] * inv * w[i];
}

// ---------------- RoPE ----------------
// q layout: g_q[row, h*192 + 128 + 2p {,+1}] ; freqs_cis: [S, 32, 2] (cos, sin)
__global__ void rope_q(float* __restrict__ q, const float* __restrict__ fc)
{
    int idx = blockIdx.x * blockDim.x + threadIdx.x;
    if (idx >= ROWS * NH * 32) return;
    int p = idx & 31;
    int h = (idx >> 5) & 15;
    int r = idx >> 9;
    int s = r & (SS - 1);
    float cs = fc[(s*32 + p)*2 + 0];
    float sn = fc[(s*32 + p)*2 + 1];
    float* base = q + (size_t)r * QDIM + h * QKH + NOPE_D + 2*p;
    float xr = base[0], xi = base[1];
    base[0] = xr*cs - xi*sn;
    base[1] = xr*sn + xi*cs;
}

__global__ void rope_k(float* __restrict__ c, const float* __restrict__ fc)
{
    int idx = blockIdx.x * blockDim.x + threadIdx.x;
    if (idx >= ROWS * 32) return;
    int p = idx & 31;
    int r = idx >> 5;
    int s = r & (SS - 1);
    float cs = fc[(s*32 + p)*2 + 0];
    float sn = fc[(s*32 + p)*2 + 1];
    float* base = c + (size_t)r * CDIM + KVRANK + 2*p;
    float xr = base[0], xi = base[1];
    base[0] = xr*cs - xi*sn;
    base[1] = xr*sn + xi*cs;
}

// ---------------- Flash attention (causal, online softmax) ----------------
// q tile 64 rows x d=192; k tile 32 x 192 (stored TRANSPOSED in smem, pad stride 34
// to avoid 16-way bank conflicts), v tile 32 x 128.
// 256 threads: ty=tid/16 owns 4 q-rows, tx=tid%16 owns 2 score-cols / 8 out-cols.
#define FAM 64
#define FAN 32
#define FAD 192
#define FAV 128
#define KTS 34   // transposed-K row stride (floats), even for float2 alignment

#define FA_SMEM_FLOATS (FAM*FAD + FAD*KTS + FAN*FAV + FAM*FAN + 2*FAM)

__global__ __launch_bounds__(256) void flash_attn(
    const float* __restrict__ gq, const float* __restrict__ gkv,
    const float* __restrict__ gc, float* __restrict__ gout)
{
    extern __shared__ float sm[];
    float* Qs = sm;                  // [64][192]
    float* KT = Qs + FAM*FAD;        // [192][34] transposed K
    float* Vs = KT + FAD*KTS;        // [32][128]
    float* Ps = Vs + FAN*FAV;        // [64][32]
    float* Ms = Ps + FAM*FAN;        // [64]
    float* Ls = Ms + FAM;            // [64]

    const int tid = threadIdx.x;
    const int tx = tid & 15, ty = tid >> 4;
    const int q0 = blockIdx.x * FAM;
    const int h  = blockIdx.y;
    const int b  = blockIdx.z;
    const int rb = b * SS;

    // load Q tile (qf = [nope | roped pe] is contiguous per head in g_q)
    const float* qp = gq + (size_t)(rb + q0) * QDIM + h * QKH;
    for (int i = tid; i < FAM*FAD; i += 256) {
        int r = i / FAD, c = i - r * FAD;
        Qs[i] = qp[(size_t)r * QDIM + c];
    }
    if (tid < FAM) { Ms[tid] = -INFINITY; Ls[tid] = 0.f; }

    float acc[4][8];
    #pragma unroll
    for (int i = 0; i < 4; i++)
        #pragma unroll
        for (int j = 0; j < 8; j++) acc[i][j] = 0.f;
    __syncthreads();

    const float scale = 0.07216878364870323f; // 1/sqrt(192)
    const int kend = q0 + FAM;

    for (int n0 = 0; n0 < kend; n0 += FAN) {
        // K tile, transposed: KT[c*34 + j] = kf[n0+j][c]
        for (int i = tid; i < FAN*FAD; i += 256) {
            int j = i / FAD, c = i - j * FAD;
            size_t row = (size_t)(rb + n0 + j);
            float v = (c < NOPE_D)
                ? gkv[row * KVDIM + h*256 + c]
                : gc [row * CDIM  + KVRANK + (c - NOPE_D)];
            KT[c * KTS + j] = v;
        }
        // V tile
        for (int i = tid; i < FAN*FAV; i += 256) {
            int j = i >> 7, c = i & 127;
            Vs[i] = gkv[(size_t)(rb + n0 + j) * KVDIM + h*256 + NOPE_D + c];
        }
        __syncthreads();

        // scores: S[4 rows][2 cols] per thread
        float sc0[4] = {0,0,0,0}, sc1[4] = {0,0,0,0};
        for (int kk = 0; kk < FAD; kk += 4) {
            float qv[4][4];
            #pragma unroll
            for (int i = 0; i < 4; i++) {
                float4 t4 = *(const float4*)&Qs[(ty*4 + i) * FAD + kk];
                qv[i][0]=t4.x; qv[i][1]=t4.y; qv[i][2]=t4.z; qv[i][3]=t4.w;
            }
            #pragma unroll
            for (int u = 0; u < 4; u++) {
                float2 k2 = *(const float2*)&KT[(kk + u) * KTS + tx*2];
                #pragma unroll
                for (int i = 0; i < 4; i++) {
                    sc0[i] = fmaf(qv[i][u], k2.x, sc0[i]);
                    sc1[i] = fmaf(qv[i][u], k2.y, sc1[i]);
                }
            }
        }

        // online softmax update (rows owned per-warp: warp w owns rows 8w..8w+7)
        #pragma unroll
        for (int i = 0; i < 4; i++) {
            int row = ty*4 + i;
            int qi = q0 + row;
            int kj = n0 + tx*2;
            float s0 = (kj     <= qi) ? sc0[i]*scale : -INFINITY;
            float s1 = (kj + 1 <= qi) ? sc1[i]*scale : -INFINITY;
            float rm = fmaxf(s0, s1);
            #pragma unroll
            for (int off = 8; off; off >>= 1)
                rm = fmaxf(rm, __shfl_xor_sync(0xffffffffu, rm, off));
            float mold = Ms[row];
            float mnew = fmaxf(mold, rm);
            float p0 = __expf(s0 - mnew);
            float p1 = __expf(s1 - mnew);
            float rs = p0 + p1;
            #pragma unroll
            for (int off = 8; off; off >>= 1)
                rs += __shfl_xor_sync(0xffffffffu, rs, off);
            float alpha = __expf(mold - mnew);
            float lnew = Ls[row] * alpha + rs;
            if (tx == 0) { Ms[row] = mnew; Ls[row] = lnew; }
            *(float2*)&Ps[row * FAN + tx*2] = make_float2(p0, p1);
            #pragma unroll
            for (int c = 0; c < 8; c++) acc[i][c] *= alpha;
        }
        __syncthreads();

        // O += P @ V  (thread: 4 rows x 8 v-cols)
        for (int j = 0; j < FAN; j++) {
            float4 v0 = *(const float4*)&Vs[j * FAV + tx*8];
            float4 v1 = *(const float4*)&Vs[j * FAV + tx*8 + 4];
            #pragma unroll
            for (int i = 0; i < 4; i++) {
                float p = Ps[(ty*4 + i) * FAN + j];
                acc[i][0] = fmaf(p, v0.x, acc[i][0]);
                acc[i][1] = fmaf(p, v0.y, acc[i][1]);
                acc[i][2] = fmaf(p, v0.z, acc[i][2]);
                acc[i][3] = fmaf(p, v0.w, acc[i][3]);
                acc[i][4] = fmaf(p, v1.x, acc[i][4]);
                acc[i][5] = fmaf(p, v1.y, acc[i][5]);
                acc[i][6] = fmaf(p, v1.z, acc[i][6]);
                acc[i][7] = fmaf(p, v1.w, acc[i][7]);
            }
        }
        __syncthreads();
    }

    // finalize: O /= l, write to g_attn[row, h*128 + c]
    #pragma unroll
    for (int i = 0; i < 4; i++) {
        int row = ty*4 + i;
        float inv = 1.f / Ls[row];
        float* op = gout + (size_t)(rb + q0 + row) * (NH*VDIM) + h*VDIM + tx*8;
        *(float4*)op       = make_float4(acc[i][0]*inv, acc[i][1]*inv, acc[i][2]*inv, acc[i][3]*inv);
        *(float4*)(op + 4) = make_float4(acc[i][4]*inv, acc[i][5]*inv, acc[i][6]*inv, acc[i][7]*inv);
    }
}

// ---------------- launcher ----------------
extern "C" void kernel_launch(void* const* d_in, const int* in_sizes, int n_in,
                              void* d_out, int out_size)
{
    const float* x     = (const float*)d_in[0];
    const float* fc    = (const float*)d_in[1];
    const float* wq_a  = (const float*)d_in[2];
    const float* qnw   = (const float*)d_in[3];
    const float* wq_b  = (const float*)d_in[4];
    const float* wkv_a = (const float*)d_in[5];
    const float* kvnw  = (const float*)d_in[6];
    const float* wkv_b = (const float*)d_in[7];
    const float* wo    = (const float*)d_in[8];
    float* out = (float*)d_out;

    float *cq, *q, *c, *kvn, *kv, *attn;
    cudaGetSymbolAddress((void**)&cq,   g_cq);
    cudaGetSymbolAddress((void**)&q,    g_q);
    cudaGetSymbolAddress((void**)&c,    g_c);
    cudaGetSymbolAddress((void**)&kvn,  g_kvn);
    cudaGetSymbolAddress((void**)&kv,   g_kv);
    cudaGetSymbolAddress((void**)&attn, g_attn);

    // 1) cq = x @ wq_a^T               [4096,1536]
    sgemm_nt<<<dim3(QRANK/GN, ROWS/GM), 256>>>(x, wq_a, cq, ROWS, QRANK, NDIM);
    // 2) rmsnorm(cq) in place
    rmsnorm_k<<<ROWS, 256>>>(cq, cq, qnw, QRANK, QRANK, QRANK);
    // 3) q = cqn @ wq_b^T              [4096,3072]
    sgemm_nt<<<dim3(QDIM/GN, ROWS/GM), 256>>>(cq, wq_b, q, ROWS, QDIM, QRANK);
    // 4) c = x @ wkv_a^T               [4096,576]
    sgemm_nt<<<dim3(CDIM/GN, ROWS/GM), 256>>>(x, wkv_a, c, ROWS, CDIM, NDIM);
    // 5) kvn = rmsnorm(c[:, :512])
    rmsnorm_k<<<ROWS, 256>>>(c, kvn, kvnw, KVRANK, CDIM, KVRANK);
    // 6) kv = kvn @ wkv_b^T            [4096,4096]
    sgemm_nt<<<dim3(KVDIM/GN, ROWS/GM), 256>>>(kvn, wkv_b, kv, ROWS, KVDIM, KVRANK);
    // 7) RoPE on q_pe (in g_q) and k_pe (in g_c)
    rope_q<<<(ROWS*NH*32 + 255)/256, 256>>>(q, fc);
    rope_k<<<(ROWS*32   + 255)/256, 256>>>(c, fc);
    // 8) flash attention -> g_attn     [4096, 2048]
    const int fa_bytes = FA_SMEM_FLOATS * (int)sizeof(float);
    cudaFuncSetAttribute(flash_attn, cudaFuncAttributeMaxDynamicSharedMemorySize, fa_bytes);
    flash_attn<<<dim3(SS/FAM, NH, BB), 256, fa_bytes>>>(q, kv, c, attn);
    // 9) out = attn @ wo^T             [4096, 2048]
    sgemm_nt<<<dim3(NDIM/GN, ROWS/GM), 256>>>(attn, wo, out, ROWS, NDIM, NH*VDIM);
}

// round 5
// speedup vs baseline: 1.5209x; 1.5161x over previous
#include <cuda_runtime.h>
#include <cuda_bf16.h>
#include <math.h>
#include <stdint.h>

// ---------------- problem constants ----------------
#define BB     2
#define SS     2048
#define NDIM   2048
#define NH     16
#define QRANK  1536
#define KVRANK 512
#define ROPE_D 64
#define NOPE_D 128
#define VDIM   128
#define QKH    192           // NOPE + ROPE
#define ROWS   (BB*SS)       // 4096
#define KVDIM  (NH*(NOPE_D+VDIM))  // 4096
#define QDIM   (NH*QKH)      // 3072
#define CDIM   (KVRANK+ROPE_D) // 576
#define ODIM   (NH*VDIM)     // 2048

typedef __nv_bfloat16 bf16;

// ---------------- scratch (device globals; no allocs allowed) ----------------
__device__ float g_cq [ROWS*QRANK];     // fp32 GEMM1 output (rmsnorm input)
__device__ float g_q  [ROWS*QDIM];      // fp32 q (attention input)
__device__ float g_c  [ROWS*CDIM];      // fp32 c (k_pe + rmsnorm input)
__device__ float g_kv [ROWS*KVDIM];     // fp32 kv (attention input)
// bf16 hi/lo operand planes
__device__ bf16 g_xh [ROWS*NDIM],   g_xl [ROWS*NDIM];
__device__ bf16 g_wqah[QRANK*NDIM], g_wqal[QRANK*NDIM];
__device__ bf16 g_wqbh[QDIM*QRANK], g_wqbl[QDIM*QRANK];
__device__ bf16 g_wkvah[CDIM*NDIM], g_wkval[CDIM*NDIM];
__device__ bf16 g_wkvbh[KVDIM*KVRANK], g_wkvbl[KVDIM*KVRANK];
__device__ bf16 g_woh[NDIM*ODIM],   g_wol[NDIM*ODIM];
__device__ bf16 g_cqh[ROWS*QRANK],  g_cql[ROWS*QRANK];
__device__ bf16 g_kvnh[ROWS*KVRANK],g_kvnl[ROWS*KVRANK];
__device__ bf16 g_ah [ROWS*ODIM],   g_al [ROWS*ODIM];

// ---------------- helpers ----------------
__device__ __forceinline__ void split1(float x, bf16& h, bf16& l) {
    h = __float2bfloat16_rn(x);
    l = __float2bfloat16_rn(x - __bfloat162float(h));
}

// split fp32 -> (hi, lo) bf16 planes, 4 elems/thread
__global__ void split_bf16_k(const float4* __restrict__ in,
                             uint2* __restrict__ hi, uint2* __restrict__ lo, int n4)
{
    int i = blockIdx.x * blockDim.x + threadIdx.x;
    if (i >= n4) return;
    float4 v = in[i];
    bf16 h0,h1,h2,h3,l0,l1,l2,l3;
    split1(v.x,h0,l0); split1(v.y,h1,l1); split1(v.z,h2,l2); split1(v.w,h3,l3);
    union { bf16 b[4]; uint2 u; } ph, pl;
    ph.b[0]=h0; ph.b[1]=h1; ph.b[2]=h2; ph.b[3]=h3;
    pl.b[0]=l0; pl.b[1]=l1; pl.b[2]=l2; pl.b[3]=l3;
    hi[i] = ph.u; lo[i] = pl.u;
}

__device__ __forceinline__ uint32_t cvta_shared_u32(const void* p) {
    return (uint32_t)__cvta_generic_to_shared(p);
}

#define CP_ASYNC16(dst, src) \
    asm volatile("cp.async.cg.shared.global [%0], [%1], 16;" :: "r"(dst), "l"(src) : "memory")
#define CP_COMMIT() asm volatile("cp.async.commit_group;" ::: "memory")
#define CP_WAIT(N)  asm volatile("cp.async.wait_group %0;" :: "n"(N) : "memory")

#define LDSM_X4(r0,r1,r2,r3,addr) \
    asm volatile("ldmatrix.sync.aligned.m8n8.x4.shared.b16 {%0,%1,%2,%3}, [%4];" \
        : "=r"(r0), "=r"(r1), "=r"(r2), "=r"(r3) : "r"(addr))

#define MMA_BF16(d, a, b) \
    asm volatile("mma.sync.aligned.m16n8k16.row.col.f32.bf16.bf16.f32 " \
        "{%0,%1,%2,%3}, {%4,%5,%6,%7}, {%8,%9}, {%0,%1,%2,%3};" \
        : "+f"((d)[0]), "+f"((d)[1]), "+f"((d)[2]), "+f"((d)[3]) \
        : "r"((a)[0]), "r"((a)[1]), "r"((a)[2]), "r"((a)[3]), "r"((b)[0]), "r"((b)[1]))

// ---------------- bf16x3 GEMM: C[M,N] = A[M,K] * B[N,K]^T (fp32 accum) ----------------
// CTA 128 x NT, K-chunk 32. Smem row = 128B: [hi k0..31 | lo k0..31], XOR-8 swizzle.
// 4-stage cp.async ring. 8 warps: 2(M) x 4(N), warp tile 64 x NT/4.
#define STAGES 4

template<int NT>
__device__ __forceinline__ void load_stage(
    const bf16* __restrict__ Ah, const bf16* __restrict__ Al,
    const bf16* __restrict__ Bh, const bf16* __restrict__ Bl,
    int K, int m0, int n0, int k0, uint32_t sA, int tid)
{
    constexpr int TOT = (128 + NT) * 8;
    #pragma unroll
    for (int i = 0; i < TOT / 256; i++) {
        int c = tid + i * 256;
        int row = c >> 3;
        int u = c & 7;               // u = plane*4 + k8group
        int plane = u >> 2, g = u & 3;
        if (row < 128) {
            const bf16* src = (plane ? Al : Ah) + (size_t)(m0 + row) * K + k0 + g * 8;
            uint32_t dst = sA + row * 128 + ((u ^ (row & 7)) << 4);
            CP_ASYNC16(dst, src);
        } else {
            int br = row - 128;
            const bf16* src = (plane ? Bl : Bh) + (size_t)(n0 + br) * K + k0 + g * 8;
            uint32_t dst = sA + 16384 + br * 128 + ((u ^ (br & 7)) << 4);
            CP_ASYNC16(dst, src);
        }
    }
}

template<int NT>
__global__ __launch_bounds__(256, 1) void gemm_bf16x3(
    const bf16* __restrict__ Ah, const bf16* __restrict__ Al,
    const bf16* __restrict__ Bh, const bf16* __restrict__ Bl,
    float* __restrict__ C, int M, int N, int K)
{
    constexpr int WN = NT / 4;       // warp N extent
    constexpr int NI = WN / 8;       // n8 frags per warp
    constexpr int CHUNK = 16384 + NT * 128;

    extern __shared__ char smem_raw[];
    const uint32_t sbase = cvta_shared_u32(smem_raw);

    const int tid = threadIdx.x;
    const int wid = tid >> 5, lane = tid & 31;
    const int wm = wid >> 2, wn = wid & 3;     // warp grid 2 x 4
    const int m0 = blockIdx.y * 128;
    const int n0 = blockIdx.x * NT;
    const int mat = lane >> 3, r8 = lane & 7;  // ldmatrix addressing role

    float acc[4][NI][4];
    #pragma unroll
    for (int i = 0; i < 4; i++)
        #pragma unroll
        for (int j = 0; j < NI; j++)
            #pragma unroll
            for (int e = 0; e < 4; e++) acc[i][j][e] = 0.f;

    const int kT = K / 32;

    // prologue: fill STAGES-1 stages
    #pragma unroll
    for (int st = 0; st < STAGES - 1; st++) {
        load_stage<NT>(Ah, Al, Bh, Bl, K, m0, n0, st * 32, sbase + st * CHUNK, tid);
        CP_COMMIT();
    }

    for (int it = 0; it < kT; it++) {
        CP_WAIT(STAGES - 2);
        __syncthreads();

        int nf = it + STAGES - 1;
        if (nf < kT)
            load_stage<NT>(Ah, Al, Bh, Bl, K, m0, n0, nf * 32,
                           sbase + (nf % STAGES) * CHUNK, tid);
        CP_COMMIT();

        const uint32_t sA = sbase + (it % STAGES) * CHUNK;
        const uint32_t sB = sA + 16384;

        #pragma unroll
        for (int s = 0; s < 2; s++) {          // two k16 steps per chunk
            const int kg = s * 2 + (mat >> 1); // k8 group for this lane's matrix
            uint32_t a_hi[4][4], a_lo[4][4];
            uint32_t b_hi[NI][2], b_lo[NI][2];

            #pragma unroll
            for (int mt = 0; mt < 4; mt++) {
                int row = wm * 64 + mt * 16 + (mat & 1) * 8 + r8;
                uint32_t rb = sA + row * 128;
                int x7 = row & 7;
                LDSM_X4(a_hi[mt][0], a_hi[mt][1], a_hi[mt][2], a_hi[mt][3],
                        rb + ((kg ^ x7) << 4));
                LDSM_X4(a_lo[mt][0], a_lo[mt][1], a_lo[mt][2], a_lo[mt][3],
                        rb + (((4 + kg) ^ x7) << 4));
            }
            #pragma unroll
            for (int p = 0; p < NI / 2; p++) {
                int row = wn * WN + p * 16 + (mat & 1) * 8 + r8;
                uint32_t rb = sB + row * 128;
                int x7 = row & 7;
                uint32_t t0, t1, t2, t3;
                LDSM_X4(t0, t1, t2, t3, rb + ((kg ^ x7) << 4));
                b_hi[2*p][0] = t0; b_hi[2*p][1] = t2;
                b_hi[2*p+1][0] = t1; b_hi[2*p+1][1] = t3;
                LDSM_X4(t0, t1, t2, t3, rb + (((4 + kg) ^ x7) << 4));
                b_lo[2*p][0] = t0; b_lo[2*p][1] = t2;
                b_lo[2*p+1][0] = t1; b_lo[2*p+1][1] = t3;
            }

            #pragma unroll
            for (int mt = 0; mt < 4; mt++)
                #pragma unroll
                for (int nt = 0; nt < NI; nt++) {
                    MMA_BF16(acc[mt][nt], a_hi[mt], b_hi[nt]);
                    MMA_BF16(acc[mt][nt], a_hi[mt], b_lo[nt]);
                    MMA_BF16(acc[mt][nt], a_lo[mt], b_hi[nt]);
                }
        }
    }

    // epilogue: C frag thread t -> rows (m, m+8), cols 2 consecutive n
    const int qm = lane >> 2, qn = (lane & 3) * 2;
    #pragma unroll
    for (int mt = 0; mt < 4; mt++)
        #pragma unroll
        for (int nt = 0; nt < NI; nt++) {
            int m = m0 + wm * 64 + mt * 16 + qm;
            int n = n0 + wn * WN + nt * 8 + qn;
            *(float2*)&C[(size_t)m * N + n]       = make_float2(acc[mt][nt][0], acc[mt][nt][1]);
            *(float2*)&C[(size_t)(m + 8) * N + n] = make_float2(acc[mt][nt][2], acc[mt][nt][3]);
        }
}

// ---------------- RMSNorm -> bf16 hi/lo planes ----------------
__global__ __launch_bounds__(256) void rmsnorm_split_k(
    const float* __restrict__ in, bf16* __restrict__ oh, bf16* __restrict__ ol,
    const float* __restrict__ w, int L, int sin)
{
    __shared__ float red[8];
    const int row = blockIdx.x;
    const float* ip = in + (size_t)row * sin;
    float ss = 0.f;
    for (int i = threadIdx.x; i < L; i += 256) {
        float v = ip[i];
        ss = fmaf(v, v, ss);
    }
    #pragma unroll
    for (int off = 16; off; off >>= 1)
        ss += __shfl_xor_sync(0xffffffffu, ss, off);
    if ((threadIdx.x & 31) == 0) red[threadIdx.x >> 5] = ss;
    __syncthreads();
    if (threadIdx.x == 0) {
        float tot = 0.f;
        #pragma unroll
        for (int i = 0; i < 8; i++) tot += red[i];
        red[0] = rsqrtf(tot / (float)L + 1e-6f);
    }
    __syncthreads();
    float inv = red[0];
    for (int i = threadIdx.x; i < L; i += 256) {
        float v = ip[i] * inv * w[i];
        bf16 h, l; split1(v, h, l);
        oh[(size_t)row * L + i] = h;
        ol[(size_t)row * L + i] = l;
    }
}

// ---------------- RoPE ----------------
__global__ void rope_q(float* __restrict__ q, const float* __restrict__ fc)
{
    int idx = blockIdx.x * blockDim.x + threadIdx.x;
    if (idx >= ROWS * NH * 32) return;
    int p = idx & 31;
    int h = (idx >> 5) & 15;
    int r = idx >> 9;
    int s = r & (SS - 1);
    float cs = fc[(s*32 + p)*2 + 0];
    float sn = fc[(s*32 + p)*2 + 1];
    float* base = q + (size_t)r * QDIM + h * QKH + NOPE_D + 2*p;
    float xr = base[0], xi = base[1];
    base[0] = xr*cs - xi*sn;
    base[1] = xr*sn + xi*cs;
}

__global__ void rope_k(float* __restrict__ c, const float* __restrict__ fc)
{
    int idx = blockIdx.x * blockDim.x + threadIdx.x;
    if (idx >= ROWS * 32) return;
    int p = idx & 31;
    int r = idx >> 5;
    int s = r & (SS - 1);
    float cs = fc[(s*32 + p)*2 + 0];
    float sn = fc[(s*32 + p)*2 + 1];
    float* base = c + (size_t)r * CDIM + KVRANK + 2*p;
    float xr = base[0], xi = base[1];
    base[0] = xr*cs - xi*sn;
    base[1] = xr*sn + xi*cs;
}

// ---------------- Flash attention (causal, online softmax, fp32) ----------------
// Output written directly as bf16 hi/lo planes (feeds the wo GEMM).
#define FAM 64
#define FAN 32
#define FAD 192
#define FAV 128
#define KTS 34

#define FA_SMEM_FLOATS (FAM*FAD + FAD*KTS + FAN*FAV + FAM*FAN + 2*FAM)

__global__ __launch_bounds__(256) void flash_attn(
    const float* __restrict__ gq, const float* __restrict__ gkv,
    const float* __restrict__ gc, bf16* __restrict__ goh, bf16* __restrict__ gol)
{
    extern __shared__ float sm[];
    float* Qs = sm;
    float* KT = Qs + FAM*FAD;
    float* Vs = KT + FAD*KTS;
    float* Ps = Vs + FAN*FAV;
    float* Ms = Ps + FAM*FAN;
    float* Ls = Ms + FAM;

    const int tid = threadIdx.x;
    const int tx = tid & 15, ty = tid >> 4;
    const int q0 = blockIdx.x * FAM;
    const int h  = blockIdx.y;
    const int b  = blockIdx.z;
    const int rb = b * SS;

    const float* qp = gq + (size_t)(rb + q0) * QDIM + h * QKH;
    for (int i = tid; i < FAM*FAD; i += 256) {
        int r = i / FAD, c = i - r * FAD;
        Qs[i] = qp[(size_t)r * QDIM + c];
    }
    if (tid < FAM) { Ms[tid] = -INFINITY; Ls[tid] = 0.f; }

    float acc[4][8];
    #pragma unroll
    for (int i = 0; i < 4; i++)
        #pragma unroll
        for (int j = 0; j < 8; j++) acc[i][j] = 0.f;
    __syncthreads();

    const float scale = 0.07216878364870323f; // 1/sqrt(192)
    const int kend = q0 + FAM;

    for (int n0 = 0; n0 < kend; n0 += FAN) {
        for (int i = tid; i < FAN*FAD; i += 256) {
            int j = i / FAD, c = i - j * FAD;
            size_t row = (size_t)(rb + n0 + j);
            float v = (c < NOPE_D)
                ? gkv[row * KVDIM + h*256 + c]
                : gc [row * CDIM  + KVRANK + (c - NOPE_D)];
            KT[c * KTS + j] = v;
        }
        for (int i = tid; i < FAN*FAV; i += 256) {
            int j = i >> 7, c = i & 127;
            Vs[i] = gkv[(size_t)(rb + n0 + j) * KVDIM + h*256 + NOPE_D + c];
        }
        __syncthreads();

        float sc0[4] = {0,0,0,0}, sc1[4] = {0,0,0,0};
        for (int kk = 0; kk < FAD; kk += 4) {
            float qv[4][4];
            #pragma unroll
            for (int i = 0; i < 4; i++) {
                float4 t4 = *(const float4*)&Qs[(ty*4 + i) * FAD + kk];
                qv[i][0]=t4.x; qv[i][1]=t4.y; qv[i][2]=t4.z; qv[i][3]=t4.w;
            }
            #pragma unroll
            for (int u = 0; u < 4; u++) {
                float2 k2 = *(const float2*)&KT[(kk + u) * KTS + tx*2];
                #pragma unroll
                for (int i = 0; i < 4; i++) {
                    sc0[i] = fmaf(qv[i][u], k2.x, sc0[i]);
                    sc1[i] = fmaf(qv[i][u], k2.y, sc1[i]);
                }
            }
        }

        #pragma unroll
        for (int i = 0; i < 4; i++) {
            int row = ty*4 + i;
            int qi = q0 + row;
            int kj = n0 + tx*2;
            float s0 = (kj     <= qi) ? sc0[i]*scale : -INFINITY;
            float s1 = (kj + 1 <= qi) ? sc1[i]*scale : -INFINITY;
            float rm = fmaxf(s0, s1);
            #pragma unroll
            for (int off = 8; off; off >>= 1)
                rm = fmaxf(rm, __shfl_xor_sync(0xffffffffu, rm, off));
            float mold = Ms[row];
            float mnew = fmaxf(mold, rm);
            float p0 = __expf(s0 - mnew);
            float p1 = __expf(s1 - mnew);
            float rs = p0 + p1;
            #pragma unroll
            for (int off = 8; off; off >>= 1)
                rs += __shfl_xor_sync(0xffffffffu, rs, off);
            float alpha = __expf(mold - mnew);
            float lnew = Ls[row] * alpha + rs;
            if (tx == 0) { Ms[row] = mnew; Ls[row] = lnew; }
            *(float2*)&Ps[row * FAN + tx*2] = make_float2(p0, p1);
            #pragma unroll
            for (int c = 0; c < 8; c++) acc[i][c] *= alpha;
        }
        __syncthreads();

        for (int j = 0; j < FAN; j++) {
            float4 v0 = *(const float4*)&Vs[j * FAV + tx*8];
            float4 v1 = *(const float4*)&Vs[j * FAV + tx*8 + 4];
            #pragma unroll
            for (int i = 0; i < 4; i++) {
                float p = Ps[(ty*4 + i) * FAN + j];
                acc[i][0] = fmaf(p, v0.x, acc[i][0]);
                acc[i][1] = fmaf(p, v0.y, acc[i][1]);
                acc[i][2] = fmaf(p, v0.z, acc[i][2]);
                acc[i][3] = fmaf(p, v0.w, acc[i][3]);
                acc[i][4] = fmaf(p, v1.x, acc[i][4]);
                acc[i][5] = fmaf(p, v1.y, acc[i][5]);
                acc[i][6] = fmaf(p, v1.z, acc[i][6]);
                acc[i][7] = fmaf(p, v1.w, acc[i][7]);
            }
        }
        __syncthreads();
    }

    // finalize: split into bf16 hi/lo planes
    #pragma unroll
    for (int i = 0; i < 4; i++) {
        int row = ty*4 + i;
        float inv = 1.f / Ls[row];
        size_t off = (size_t)(rb + q0 + row) * ODIM + h*VDIM + tx*8;
        union { bf16 b[8]; uint4 u; } ph, pl;
        #pragma unroll
        for (int c = 0; c < 8; c++) {
            float v = acc[i][c] * inv;
            bf16 hh, ll; split1(v, hh, ll);
            ph.b[c] = hh; pl.b[c] = ll;
        }
        *(uint4*)&goh[off] = ph.u;
        *(uint4*)&gol[off] = pl.u;
    }
}

// ---------------- launcher ----------------
static inline void split_pass(const float* src, bf16* hi, bf16* lo, size_t n)
{
    int n4 = (int)(n / 4);
    split_bf16_k<<<(n4 + 255) / 256, 256>>>((const float4*)src, (uint2*)hi, (uint2*)lo, n4);
}

extern "C" void kernel_launch(void* const* d_in, const int* in_sizes, int n_in,
                              void* d_out, int out_size)
{
    const float* x     = (const float*)d_in[0];
    const float* fc    = (const float*)d_in[1];
    const float* wq_a  = (const float*)d_in[2];
    const float* qnw   = (const float*)d_in[3];
    const float* wq_b  = (const float*)d_in[4];
    const float* wkv_a = (const float*)d_in[5];
    const float* kvnw  = (const float*)d_in[6];
    const float* wkv_b = (const float*)d_in[7];
    const float* wo    = (const float*)d_in[8];
    float* out = (float*)d_out;

    float *cq, *q, *c, *kv;
    bf16 *xh,*xl, *wqah,*wqal, *wqbh,*wqbl, *wkvah,*wkval, *wkvbh,*wkvbl, *woh,*wol;
    bf16 *cqh,*cql, *kvnh,*kvnl, *ah,*al;
    cudaGetSymbolAddress((void**)&cq,  g_cq);
    cudaGetSymbolAddress((void**)&q,   g_q);
    cudaGetSymbolAddress((void**)&c,   g_c);
    cudaGetSymbolAddress((void**)&kv,  g_kv);
    cudaGetSymbolAddress((void**)&xh,  g_xh);   cudaGetSymbolAddress((void**)&xl,  g_xl);
    cudaGetSymbolAddress((void**)&wqah,g_wqah); cudaGetSymbolAddress((void**)&wqal,g_wqal);
    cudaGetSymbolAddress((void**)&wqbh,g_wqbh); cudaGetSymbolAddress((void**)&wqbl,g_wqbl);
    cudaGetSymbolAddress((void**)&wkvah,g_wkvah); cudaGetSymbolAddress((void**)&wkval,g_wkval);
    cudaGetSymbolAddress((void**)&wkvbh,g_wkvbh); cudaGetSymbolAddress((void**)&wkvbl,g_wkvbl);
    cudaGetSymbolAddress((void**)&woh, g_woh);  cudaGetSymbolAddress((void**)&wol, g_wol);
    cudaGetSymbolAddress((void**)&cqh, g_cqh);  cudaGetSymbolAddress((void**)&cql, g_cql);
    cudaGetSymbolAddress((void**)&kvnh,g_kvnh); cudaGetSymbolAddress((void**)&kvnl,g_kvnl);
    cudaGetSymbolAddress((void**)&ah,  g_ah);   cudaGetSymbolAddress((void**)&al,  g_al);

    const int smem128 = STAGES * (16384 + 128*128); // 131072
    const int smem64  = STAGES * (16384 + 64*128);  // 98304
    cudaFuncSetAttribute(gemm_bf16x3<128>, cudaFuncAttributeMaxDynamicSharedMemorySize, smem128);
    cudaFuncSetAttribute(gemm_bf16x3<64>,  cudaFuncAttributeMaxDynamicSharedMemorySize, smem64);

    // 0) split operands to bf16 hi/lo planes
    split_pass(x,     xh,   xl,   (size_t)ROWS * NDIM);
    split_pass(wq_a,  wqah, wqal, (size_t)QRANK * NDIM);
    split_pass(wq_b,  wqbh, wqbl, (size_t)QDIM * QRANK);
    split_pass(wkv_a, wkvah,wkval,(size_t)CDIM * NDIM);
    split_pass(wkv_b, wkvbh,wkvbl,(size_t)KVDIM * KVRANK);
    split_pass(wo,    woh,  wol,  (size_t)NDIM * ODIM);

    // 1) cq = x @ wq_a^T               [4096,1536] K=2048
    gemm_bf16x3<128><<<dim3(QRANK/128, ROWS/128), 256, smem128>>>(xh, xl, wqah, wqal, cq, ROWS, QRANK, NDIM);
    // 2) rmsnorm(cq) -> bf16 planes
    rmsnorm_split_k<<<ROWS, 256>>>(cq, cqh, cql, qnw, QRANK, QRANK);
    // 3) q = cqn @ wq_b^T              [4096,3072] K=1536
    gemm_bf16x3<128><<<dim3(QDIM/128, ROWS/128), 256, smem128>>>(cqh, cql, wqbh, wqbl, q, ROWS, QDIM, QRANK);
    // 4) c = x @ wkv_a^T               [4096,576] K=2048
    gemm_bf16x3<64><<<dim3(CDIM/64, ROWS/128), 256, smem64>>>(xh, xl, wkvah, wkval, c, ROWS, CDIM, NDIM);
    // 5) kvn = rmsnorm(c[:, :512]) -> bf16 planes
    rmsnorm_split_k<<<ROWS, 256>>>(c, kvnh, kvnl, kvnw, KVRANK, CDIM);
    // 6) kv = kvn @ wkv_b^T            [4096,4096] K=512
    gemm_bf16x3<128><<<dim3(KVDIM/128, ROWS/128), 256, smem128>>>(kvnh, kvnl, wkvbh, wkvbl, kv, ROWS, KVDIM, KVRANK);
    // 7) RoPE on q_pe and k_pe (fp32)
    rope_q<<<(ROWS*NH*32 + 255)/256, 256>>>(q, fc);
    rope_k<<<(ROWS*32   + 255)/256, 256>>>(c, fc);
    // 8) flash attention -> bf16 hi/lo planes
    const int fa_bytes = FA_SMEM_FLOATS * (int)sizeof(float);
    cudaFuncSetAttribute(flash_attn, cudaFuncAttributeMaxDynamicSharedMemorySize, fa_bytes);
    flash_attn<<<dim3(SS/FAM, NH, BB), 256, fa_bytes>>>(q, kv, c, ah, al);
    // 9) out = attn @ wo^T             [4096,2048] K=2048
    gemm_bf16x3<128><<<dim3(NDIM/128, ROWS/128), 256, smem128>>>(ah, al, woh, wol, out, ROWS, NDIM, ODIM);
}

// round 6
// speedup vs baseline: 3.0722x; 2.0200x over previous
#include <cuda_runtime.h>
#include <cuda_bf16.h>
#include <math.h>
#include <stdint.h>

// ---------------- problem constants ----------------
#define BB     2
#define SS     2048
#define NDIM   2048
#define NH     16
#define QRANK  1536
#define KVRANK 512
#define ROPE_D 64
#define NOPE_D 128
#define VDIM   128
#define QKH    192           // NOPE + ROPE
#define ROWS   (BB*SS)       // 4096
#define KVDIM  (NH*(NOPE_D+VDIM))  // 4096
#define QDIM   (NH*QKH)      // 3072
#define CDIM   (KVRANK+ROPE_D) // 576
#define ODIM   (NH*VDIM)     // 2048

typedef __nv_bfloat16 bf16;

// ---------------- scratch (device globals; no allocs allowed) ----------------
__device__ float g_cq [ROWS*QRANK];
__device__ float g_q  [ROWS*QDIM];
__device__ float g_c  [ROWS*CDIM];
__device__ float g_kv [ROWS*KVDIM];
// bf16 hi/lo operand planes for GEMMs
__device__ bf16 g_xh [ROWS*NDIM],   g_xl [ROWS*NDIM];
__device__ bf16 g_wqah[QRANK*NDIM], g_wqal[QRANK*NDIM];
__device__ bf16 g_wqbh[QDIM*QRANK], g_wqbl[QDIM*QRANK];
__device__ bf16 g_wkvah[CDIM*NDIM], g_wkval[CDIM*NDIM];
__device__ bf16 g_wkvbh[KVDIM*KVRANK], g_wkvbl[KVDIM*KVRANK];
__device__ bf16 g_woh[NDIM*ODIM],   g_wol[NDIM*ODIM];
__device__ bf16 g_cqh[ROWS*QRANK],  g_cql[ROWS*QRANK];
__device__ bf16 g_kvnh[ROWS*KVRANK],g_kvnl[ROWS*KVRANK];
__device__ bf16 g_ah [ROWS*ODIM],   g_al [ROWS*ODIM];
// attention operands (head-major layouts)
__device__ bf16 g_qb [NH*ROWS*QKH];     // roped q, bf16
__device__ bf16 g_kb [NH*ROWS*QKH];     // k_nope | roped k_pe, bf16
__device__ bf16 g_vhp[NH*ROWS*VDIM];    // v hi plane
__device__ bf16 g_vlp[NH*ROWS*VDIM];    // v lo plane

// ---------------- helpers ----------------
__device__ __forceinline__ void split1(float x, bf16& h, bf16& l) {
    h = __float2bfloat16_rn(x);
    l = __float2bfloat16_rn(x - __bfloat162float(h));
}

__device__ __forceinline__ void split_pack(float x, float y, uint32_t& hi, uint32_t& lo) {
    bf16 hx, lx, hy, ly;
    split1(x, hx, lx); split1(y, hy, ly);
    hi = ((uint32_t)__bfloat16_as_ushort(hy) << 16) | __bfloat16_as_ushort(hx);
    lo = ((uint32_t)__bfloat16_as_ushort(ly) << 16) | __bfloat16_as_ushort(lx);
}

// fast exp2 on FMA pipe (x <= 0), rel err ~1e-6
__device__ __forceinline__ float fexp2(float x) {
    x = fmaxf(x, -126.f);
    float fl = floorf(x);
    float f = x - fl;
    float p = 1.535336188319500e-4f;
    p = fmaf(p, f, 1.339887440266574e-3f);
    p = fmaf(p, f, 9.618437357674640e-3f);
    p = fmaf(p, f, 5.550332471162809e-2f);
    p = fmaf(p, f, 2.402264791363012e-1f);
    p = fmaf(p, f, 6.931472028550421e-1f);
    p = fmaf(p, f, 1.0f);
    return p * __int_as_float(((int)fl + 127) << 23);
}

__global__ void split_bf16_k(const float4* __restrict__ in,
                             uint2* __restrict__ hi, uint2* __restrict__ lo, int n4)
{
    int i = blockIdx.x * blockDim.x + threadIdx.x;
    if (i >= n4) return;
    float4 v = in[i];
    bf16 h0,h1,h2,h3,l0,l1,l2,l3;
    split1(v.x,h0,l0); split1(v.y,h1,l1); split1(v.z,h2,l2); split1(v.w,h3,l3);
    union { bf16 b[4]; uint2 u; } ph, pl;
    ph.b[0]=h0; ph.b[1]=h1; ph.b[2]=h2; ph.b[3]=h3;
    pl.b[0]=l0; pl.b[1]=l1; pl.b[2]=l2; pl.b[3]=l3;
    hi[i] = ph.u; lo[i] = pl.u;
}

__device__ __forceinline__ uint32_t cvta_shared_u32(const void* p) {
    return (uint32_t)__cvta_generic_to_shared(p);
}

#define CP_ASYNC16(dst, src) \
    asm volatile("cp.async.cg.shared.global [%0], [%1], 16;" :: "r"(dst), "l"(src) : "memory")
#define CP_COMMIT() asm volatile("cp.async.commit_group;" ::: "memory")
#define CP_WAIT(N)  asm volatile("cp.async.wait_group %0;" :: "n"(N) : "memory")

#define LDSM_X4(r0,r1,r2,r3,addr) \
    asm volatile("ldmatrix.sync.aligned.m8n8.x4.shared.b16 {%0,%1,%2,%3}, [%4];" \
        : "=r"(r0), "=r"(r1), "=r"(r2), "=r"(r3) : "r"(addr))

#define LDSM_X4T(r0,r1,r2,r3,addr) \
    asm volatile("ldmatrix.sync.aligned.m8n8.x4.trans.shared.b16 {%0,%1,%2,%3}, [%4];" \
        : "=r"(r0), "=r"(r1), "=r"(r2), "=r"(r3) : "r"(addr))

#define MMA_BF16(d, a, b) \
    asm volatile("mma.sync.aligned.m16n8k16.row.col.f32.bf16.bf16.f32 " \
        "{%0,%1,%2,%3}, {%4,%5,%6,%7}, {%8,%9}, {%0,%1,%2,%3};" \
        : "+f"((d)[0]), "+f"((d)[1]), "+f"((d)[2]), "+f"((d)[3]) \
        : "r"((a)[0]), "r"((a)[1]), "r"((a)[2]), "r"((a)[3]), "r"((b)[0]), "r"((b)[1]))

// ---------------- bf16x3 GEMM: C[M,N] = A[M,K] * B[N,K]^T (fp32 accum) ----------------
#define STAGES 4

template<int NT>
__device__ __forceinline__ void load_stage(
    const bf16* __restrict__ Ah, const bf16* __restrict__ Al,
    const bf16* __restrict__ Bh, const bf16* __restrict__ Bl,
    int K, int m0, int n0, int k0, uint32_t sA, int tid)
{
    constexpr int TOT = (128 + NT) * 8;
    #pragma unroll
    for (int i = 0; i < TOT / 256; i++) {
        int c = tid + i * 256;
        int row = c >> 3;
        int u = c & 7;
        int plane = u >> 2, g = u & 3;
        if (row < 128) {
            const bf16* src = (plane ? Al : Ah) + (size_t)(m0 + row) * K + k0 + g * 8;
            uint32_t dst = sA + row * 128 + ((u ^ (row & 7)) << 4);
            CP_ASYNC16(dst, src);
        } else {
            int br = row - 128;
            const bf16* src = (plane ? Bl : Bh) + (size_t)(n0 + br) * K + k0 + g * 8;
            uint32_t dst = sA + 16384 + br * 128 + ((u ^ (br & 7)) << 4);
            CP_ASYNC16(dst, src);
        }
    }
}

template<int NT>
__global__ __launch_bounds__(256, 1) void gemm_bf16x3(
    const bf16* __restrict__ Ah, const bf16* __restrict__ Al,
    const bf16* __restrict__ Bh, const bf16* __restrict__ Bl,
    float* __restrict__ C, int M, int N, int K)
{
    constexpr int WN = NT / 4;
    constexpr int NI = WN / 8;
    constexpr int CHUNK = 16384 + NT * 128;

    extern __shared__ char smem_raw[];
    const uint32_t sbase = cvta_shared_u32(smem_raw);

    const int tid = threadIdx.x;
    const int wid = tid >> 5, lane = tid & 31;
    const int wm = wid >> 2, wn = wid & 3;
    const int m0 = blockIdx.y * 128;
    const int n0 = blockIdx.x * NT;
    const int mat = lane >> 3, r8 = lane & 7;

    float acc[4][NI][4];
    #pragma unroll
    for (int i = 0; i < 4; i++)
        #pragma unroll
        for (int j = 0; j < NI; j++)
            #pragma unroll
            for (int e = 0; e < 4; e++) acc[i][j][e] = 0.f;

    const int kT = K / 32;

    #pragma unroll
    for (int st = 0; st < STAGES - 1; st++) {
        load_stage<NT>(Ah, Al, Bh, Bl, K, m0, n0, st * 32, sbase + st * CHUNK, tid);
        CP_COMMIT();
    }

    for (int it = 0; it < kT; it++) {
        CP_WAIT(STAGES - 2);
        __syncthreads();

        int nf = it + STAGES - 1;
        if (nf < kT)
            load_stage<NT>(Ah, Al, Bh, Bl, K, m0, n0, nf * 32,
                           sbase + (nf % STAGES) * CHUNK, tid);
        CP_COMMIT();

        const uint32_t sA = sbase + (it % STAGES) * CHUNK;
        const uint32_t sB = sA + 16384;

        #pragma unroll
        for (int s = 0; s < 2; s++) {
            const int kg = s * 2 + (mat >> 1);
            uint32_t a_hi[4][4], a_lo[4][4];
            uint32_t b_hi[NI][2], b_lo[NI][2];

            #pragma unroll
            for (int mt = 0; mt < 4; mt++) {
                int row = wm * 64 + mt * 16 + (mat & 1) * 8 + r8;
                uint32_t rb = sA + row * 128;
                int x7 = row & 7;
                LDSM_X4(a_hi[mt][0], a_hi[mt][1], a_hi[mt][2], a_hi[mt][3],
                        rb + ((kg ^ x7) << 4));
                LDSM_X4(a_lo[mt][0], a_lo[mt][1], a_lo[mt][2], a_lo[mt][3],
                        rb + (((4 + kg) ^ x7) << 4));
            }
            #pragma unroll
            for (int p = 0; p < NI / 2; p++) {
                int row = wn * WN + p * 16 + (mat & 1) * 8 + r8;
                uint32_t rb = sB + row * 128;
                int x7 = row & 7;
                uint32_t t0, t1, t2, t3;
                LDSM_X4(t0, t1, t2, t3, rb + ((kg ^ x7) << 4));
                b_hi[2*p][0] = t0; b_hi[2*p][1] = t2;
                b_hi[2*p+1][0] = t1; b_hi[2*p+1][1] = t3;
                LDSM_X4(t0, t1, t2, t3, rb + (((4 + kg) ^ x7) << 4));
                b_lo[2*p][0] = t0; b_lo[2*p][1] = t2;
                b_lo[2*p+1][0] = t1; b_lo[2*p+1][1] = t3;
            }

            #pragma unroll
            for (int mt = 0; mt < 4; mt++)
                #pragma unroll
                for (int nt = 0; nt < NI; nt++) {
                    MMA_BF16(acc[mt][nt], a_hi[mt], b_hi[nt]);
                    MMA_BF16(acc[mt][nt], a_hi[mt], b_lo[nt]);
                    MMA_BF16(acc[mt][nt], a_lo[mt], b_hi[nt]);
                }
        }
    }

    const int qm = lane >> 2, qn = (lane & 3) * 2;
    #pragma unroll
    for (int mt = 0; mt < 4; mt++)
        #pragma unroll
        for (int nt = 0; nt < NI; nt++) {
            int m = m0 + wm * 64 + mt * 16 + qm;
            int n = n0 + wn * WN + nt * 8 + qn;
            *(float2*)&C[(size_t)m * N + n]       = make_float2(acc[mt][nt][0], acc[mt][nt][1]);
            *(float2*)&C[(size_t)(m + 8) * N + n] = make_float2(acc[mt][nt][2], acc[mt][nt][3]);
        }
}

// ---------------- RMSNorm -> bf16 hi/lo planes ----------------
__global__ __launch_bounds__(256) void rmsnorm_split_k(
    const float* __restrict__ in, bf16* __restrict__ oh, bf16* __restrict__ ol,
    const float* __restrict__ w, int L, int sin)
{
    __shared__ float red[8];
    const int row = blockIdx.x;
    const float* ip = in + (size_t)row * sin;
    float ss = 0.f;
    for (int i = threadIdx.x; i < L; i += 256) {
        float v = ip[i];
        ss = fmaf(v, v, ss);
    }
    #pragma unroll
    for (int off = 16; off; off >>= 1)
        ss += __shfl_xor_sync(0xffffffffu, ss, off);
    if ((threadIdx.x & 31) == 0) red[threadIdx.x >> 5] = ss;
    __syncthreads();
    if (threadIdx.x == 0) {
        float tot = 0.f;
        #pragma unroll
        for (int i = 0; i < 8; i++) tot += red[i];
        red[0] = rsqrtf(tot / (float)L + 1e-6f);
    }
    __syncthreads();
    float inv = red[0];
    for (int i = threadIdx.x; i < L; i += 256) {
        float v = ip[i] * inv * w[i];
        bf16 h, l; split1(v, h, l);
        oh[(size_t)row * L + i] = h;
        ol[(size_t)row * L + i] = l;
    }
}

// ---------------- attention operand conversion (rope fused) ----------------
// g_qb[h][row][192] <- rope(g_q[row][h*192+...])
__global__ void qconv_k(const float* __restrict__ q, const float* __restrict__ fc,
                        bf16* __restrict__ qb)
{
    int idx = blockIdx.x * blockDim.x + threadIdx.x;
    if (idx >= NH * ROWS * 96) return;
    int p = idx % 96;
    int rowh = idx / 96;
    int row = rowh & (ROWS - 1);
    int h = rowh >> 12;           // ROWS = 4096 = 2^12
    int s = row & (SS - 1);
    const float* src = q + (size_t)row * QDIM + h * QKH + 2 * p;
    float v0 = src[0], v1 = src[1];
    if (p >= 64) {
        int pp = p - 64;
        float cs = fc[(s * 32 + pp) * 2 + 0];
        float sn = fc[(s * 32 + pp) * 2 + 1];
        float r = v0 * cs - v1 * sn;
        float i2 = v0 * sn + v1 * cs;
        v0 = r; v1 = i2;
    }
    __nv_bfloat162* dst = (__nv_bfloat162*)(qb + ((size_t)h * ROWS + row) * QKH + 2 * p);
    *dst = __floats2bfloat162_rn(v0, v1);
}

// g_kb[h][row][192] <- [k_nope from g_kv | rope(k_pe from g_c)]
__global__ void kconv_k(const float* __restrict__ kv, const float* __restrict__ c,
                        const float* __restrict__ fc, bf16* __restrict__ kb)
{
    int idx = blockIdx.x * blockDim.x + threadIdx.x;
    if (idx >= NH * ROWS * 96) return;
    int p = idx % 96;
    int rowh = idx / 96;
    int row = rowh & (ROWS - 1);
    int h = rowh >> 12;
    int s = row & (SS - 1);
    float v0, v1;
    if (p < 64) {
        const float* src = kv + (size_t)row * KVDIM + h * 256 + 2 * p;
        v0 = src[0]; v1 = src[1];
    } else {
        int pp = p - 64;
        const float* src = c + (size_t)row * CDIM + KVRANK + 2 * pp;
        float a = src[0], b = src[1];
        float cs = fc[(s * 32 + pp) * 2 + 0];
        float sn = fc[(s * 32 + pp) * 2 + 1];
        v0 = a * cs - b * sn;
        v1 = a * sn + b * cs;
    }
    __nv_bfloat162* dst = (__nv_bfloat162*)(kb + ((size_t)h * ROWS + row) * QKH + 2 * p);
    *dst = __floats2bfloat162_rn(v0, v1);
}

// g_vhp/g_vlp[h][row][128] <- split(g_kv v part)
__global__ void vconv_k(const float* __restrict__ kv,
                        bf16* __restrict__ vh, bf16* __restrict__ vl)
{
    int idx = blockIdx.x * blockDim.x + threadIdx.x;
    if (idx >= NH * ROWS * 64) return;
    int p = idx & 63;
    int rowh = idx >> 6;
    int row = rowh & (ROWS - 1);
    int h = rowh >> 12;
    const float* src = kv + (size_t)row * KVDIM + h * 256 + 128 + 2 * p;
    bf16 h0, l0, h1, l1;
    split1(src[0], h0, l0);
    split1(src[1], h1, l1);
    size_t off = ((size_t)h * ROWS + row) * VDIM + 2 * p;
    union { bf16 b[2]; uint32_t u; } t;
    t.b[0] = h0; t.b[1] = h1; *(uint32_t*)(vh + off) = t.u;
    t.b[0] = l0; t.b[1] = l1; *(uint32_t*)(vl + off) = t.u;
}

// ---------------- tensor-core flash attention ----------------
// q-tile 128 rows, 8 warps x m16; key tiles of 64; D=192; V hi/lo bf16x3 for P@V.
// smem (bf16 elems): Q 128x200, K[2] 64x200, Vh[2]/Vl[2] 64x136.
#define ATT_SMEM_BYTES ((128*200 + 2*64*200 + 4*64*136) * 2)

__global__ __launch_bounds__(256, 1) void attn_mma(
    const bf16* __restrict__ gq, const bf16* __restrict__ gk,
    const bf16* __restrict__ gvh, const bf16* __restrict__ gvl,
    bf16* __restrict__ goh, bf16* __restrict__ gol)
{
    extern __shared__ bf16 asm_[];
    const uint32_t sQ  = cvta_shared_u32(asm_);
    const uint32_t sK  = sQ  + 128 * 200 * 2;
    const uint32_t sVh = sK  + 2 * 64 * 200 * 2;
    const uint32_t sVl = sVh + 2 * 64 * 136 * 2;

    const int tid = threadIdx.x;
    const int wid = tid >> 5, lane = tid & 31;
    const int qt = gridDim.x - 1 - blockIdx.x;   // reversed: biggest work first
    const int q0 = qt * 128;
    const int h  = blockIdx.y;
    const int b  = blockIdx.z;
    const size_t hb = (size_t)h * ROWS + b * SS;

    // Q tile via cp.async: 128 rows x 24 16B-units
    {
        const bf16* qbase = gq + (hb + q0) * QKH;
        for (int i = tid; i < 3072; i += 256) {
            int row = i / 24, u = i - row * 24;
            CP_ASYNC16(sQ + (row * 200 + u * 8) * 2, qbase + row * QKH + u * 8);
        }
    }

    const int nT = q0 / 64 + 2;

    // tile loader
    auto load_tile = [&](int n0, int buf) {
        const bf16* kbase = gk + (hb + n0) * QKH;
        uint32_t kd = sK + buf * (64 * 200 * 2);
        for (int i = tid; i < 1536; i += 256) {
            int row = i / 24, u = i - row * 24;
            CP_ASYNC16(kd + (row * 200 + u * 8) * 2, kbase + row * QKH + u * 8);
        }
        const bf16* vhb = gvh + (hb + n0) * VDIM;
        const bf16* vlb = gvl + (hb + n0) * VDIM;
        uint32_t vhd = sVh + buf * (64 * 136 * 2);
        uint32_t vld = sVl + buf * (64 * 136 * 2);
        for (int i = tid; i < 1024; i += 256) {
            int row = i >> 4, u = i & 15;
            uint32_t doff = (row * 136 + u * 8) * 2;
            CP_ASYNC16(vhd + doff, vhb + row * VDIM + u * 8);
            CP_ASYNC16(vld + doff, vlb + row * VDIM + u * 8);
        }
    };

    load_tile(0, 0);
    CP_COMMIT();

    // per-thread state
    float out[16][4];
    #pragma unroll
    for (int f = 0; f < 16; f++)
        #pragma unroll
        for (int e = 0; e < 4; e++) out[f][e] = 0.f;
    float m0 = -1e30f, m1 = -1e30f, l0 = 0.f, l1 = 0.f;

    const int mat = lane >> 3, r8 = lane & 7;
    const uint32_t aQ = sQ + ((wid * 16 + (lane & 15)) * 200 + (lane >> 4) * 8) * 2;
    const float sc2 = 0.07216878364870323f * 1.4426950408889634f;
    const int growA = q0 + wid * 16 + (lane >> 2);

    for (int t = 0; t < nT; t++) {
        const int buf = t & 1;
        if (t + 1 < nT) load_tile(64 * (t + 1), buf ^ 1);
        CP_COMMIT();
        CP_WAIT(1);
        __syncthreads();

        const int n0 = 64 * t;
        const bool active = (n0 <= q0 + wid * 16 + 15);
        if (active) {
            // ---- S = Q @ K^T ----
            float s[8][4];
            #pragma unroll
            for (int f = 0; f < 8; f++)
                #pragma unroll
                for (int e = 0; e < 4; e++) s[f][e] = 0.f;

            const uint32_t kB = sK + buf * (64 * 200 * 2)
                              + (((mat >> 1) * 8 + r8) * 200 + (mat & 1) * 8) * 2;
            #pragma unroll
            for (int kt = 0; kt < 12; kt++) {
                uint32_t a[4];
                LDSM_X4(a[0], a[1], a[2], a[3], aQ + kt * 32);
                #pragma unroll
                for (int g = 0; g < 4; g++) {
                    uint32_t b0, b1, b2, b3;
                    LDSM_X4(b0, b1, b2, b3, kB + (g * 16 * 200) * 2 + kt * 32);
                    uint32_t bb0[2] = {b0, b1}, bb1[2] = {b2, b3};
                    MMA_BF16(s[2*g],   a, bb0);
                    MMA_BF16(s[2*g+1], a, bb1);
                }
            }

            // ---- online softmax (log2 domain) ----
            const bool needmask = (n0 + 63 > q0 + wid * 16);
            const int colb = n0 + 2 * (lane & 3);
            float rm0 = -1e30f, rm1 = -1e30f;
            #pragma unroll
            for (int f = 0; f < 8; f++) {
                #pragma unroll
                for (int j = 0; j < 2; j++) {
                    int col = colb + f * 8 + j;
                    float z0 = s[f][j]     * sc2;
                    float z1 = s[f][2 + j] * sc2;
                    if (needmask) {
                        if (col > growA)     z0 = -1e30f;
                        if (col > growA + 8) z1 = -1e30f;
                    }
                    s[f][j] = z0; s[f][2 + j] = z1;
                    rm0 = fmaxf(rm0, z0); rm1 = fmaxf(rm1, z1);
                }
            }
            rm0 = fmaxf(rm0, __shfl_xor_sync(0xffffffffu, rm0, 1));
            rm0 = fmaxf(rm0, __shfl_xor_sync(0xffffffffu, rm0, 2));
            rm1 = fmaxf(rm1, __shfl_xor_sync(0xffffffffu, rm1, 1));
            rm1 = fmaxf(rm1, __shfl_xor_sync(0xffffffffu, rm1, 2));
            float mn0 = fmaxf(m0, rm0), mn1 = fmaxf(m1, rm1);
            float al0 = fexp2(m0 - mn0), al1 = fexp2(m1 - mn1);
            m0 = mn0; m1 = mn1;

            float rs0 = 0.f, rs1 = 0.f;
            #pragma unroll
            for (int f = 0; f < 8; f++) {
                #pragma unroll
                for (int j = 0; j < 2; j++) {
                    float p0 = fexp2(s[f][j]     - mn0);
                    float p1 = fexp2(s[f][2 + j] - mn1);
                    s[f][j] = p0; s[f][2 + j] = p1;
                    rs0 += p0; rs1 += p1;
                }
            }
            rs0 += __shfl_xor_sync(0xffffffffu, rs0, 1);
            rs0 += __shfl_xor_sync(0xffffffffu, rs0, 2);
            rs1 += __shfl_xor_sync(0xffffffffu, rs1, 1);
            rs1 += __shfl_xor_sync(0xffffffffu, rs1, 2);
            l0 = l0 * al0 + rs0;
            l1 = l1 * al1 + rs1;

            #pragma unroll
            for (int f = 0; f < 16; f++) {
                out[f][0] *= al0; out[f][1] *= al0;
                out[f][2] *= al1; out[f][3] *= al1;
            }

            // ---- O += P @ V (bf16x3) ----
            const uint32_t vOff = (((mat & 1) * 8 + r8) * 136 + (mat >> 1) * 8) * 2;
            const uint32_t vhB = sVh + buf * (64 * 136 * 2) + vOff;
            const uint32_t vlB = sVl + buf * (64 * 136 * 2) + vOff;
            #pragma unroll
            for (int kt = 0; kt < 4; kt++) {
                uint32_t ah[4], alr[4];
                split_pack(s[2*kt][0],   s[2*kt][1],   ah[0], alr[0]);
                split_pack(s[2*kt][2],   s[2*kt][3],   ah[1], alr[1]);
                split_pack(s[2*kt+1][0], s[2*kt+1][1], ah[2], alr[2]);
                split_pack(s[2*kt+1][2], s[2*kt+1][3], ah[3], alr[3]);
                const uint32_t rowOff = (kt * 16 * 136) * 2;
                #pragma unroll
                for (int gv = 0; gv < 8; gv++) {
                    uint32_t h0, h1, h2, h3, u0, u1, u2, u3;
                    LDSM_X4T(h0, h1, h2, h3, vhB + rowOff + gv * 32);
                    LDSM_X4T(u0, u1, u2, u3, vlB + rowOff + gv * 32);
                    uint32_t bh0[2] = {h0, h1}, bh1[2] = {h2, h3};
                    uint32_t bl0[2] = {u0, u1}, bl1[2] = {u2, u3};
                    MMA_BF16(out[2*gv],   ah,  bh0);
                    MMA_BF16(out[2*gv],   ah,  bl0);
                    MMA_BF16(out[2*gv],   alr, bh0);
                    MMA_BF16(out[2*gv+1], ah,  bh1);
                    MMA_BF16(out[2*gv+1], ah,  bl1);
                    MMA_BF16(out[2*gv+1], alr, bh1);
                }
            }
        }
        __syncthreads();
    }

    // ---- finalize: O /= l, split hi/lo, store ----
    float inv0 = 1.f / l0, inv1 = 1.f / l1;
    size_t r0g = (size_t)(b * SS + q0 + wid * 16 + (lane >> 2));
    size_t base0 = r0g * ODIM + h * VDIM + 2 * (lane & 3);
    size_t base1 = base0 + 8 * (size_t)ODIM;
    #pragma unroll
    for (int f = 0; f < 16; f++) {
        uint32_t hi, lo;
        split_pack(out[f][0] * inv0, out[f][1] * inv0, hi, lo);
        *(uint32_t*)&goh[base0 + f * 8] = hi;
        *(uint32_t*)&gol[base0 + f * 8] = lo;
        split_pack(out[f][2] * inv1, out[f][3] * inv1, hi, lo);
        *(uint32_t*)&goh[base1 + f * 8] = hi;
        *(uint32_t*)&gol[base1 + f * 8] = lo;
    }
}

// ---------------- launcher ----------------
static inline void split_pass(const float* src, bf16* hi, bf16* lo, size_t n)
{
    int n4 = (int)(n / 4);
    split_bf16_k<<<(n4 + 255) / 256, 256>>>((const float4*)src, (uint2*)hi, (uint2*)lo, n4);
}

extern "C" void kernel_launch(void* const* d_in, const int* in_sizes, int n_in,
                              void* d_out, int out_size)
{
    const float* x     = (const float*)d_in[0];
    const float* fc    = (const float*)d_in[1];
    const float* wq_a  = (const float*)d_in[2];
    const float* qnw   = (const float*)d_in[3];
    const float* wq_b  = (const float*)d_in[4];
    const float* wkv_a = (const float*)d_in[5];
    const float* kvnw  = (const float*)d_in[6];
    const float* wkv_b = (const float*)d_in[7];
    const float* wo    = (const float*)d_in[8];
    float* out = (float*)d_out;

    float *cq, *q, *c, *kv;
    bf16 *xh,*xl, *wqah,*wqal, *wqbh,*wqbl, *wkvah,*wkval, *wkvbh,*wkvbl, *woh,*wol;
    bf16 *cqh,*cql, *kvnh,*kvnl, *ah,*al, *qb,*kb,*vh,*vl;
    cudaGetSymbolAddress((void**)&cq,  g_cq);
    cudaGetSymbolAddress((void**)&q,   g_q);
    cudaGetSymbolAddress((void**)&c,   g_c);
    cudaGetSymbolAddress((void**)&kv,  g_kv);
    cudaGetSymbolAddress((void**)&xh,  g_xh);   cudaGetSymbolAddress((void**)&xl,  g_xl);
    cudaGetSymbolAddress((void**)&wqah,g_wqah); cudaGetSymbolAddress((void**)&wqal,g_wqal);
    cudaGetSymbolAddress((void**)&wqbh,g_wqbh); cudaGetSymbolAddress((void**)&wqbl,g_wqbl);
    cudaGetSymbolAddress((void**)&wkvah,g_wkvah); cudaGetSymbolAddress((void**)&wkval,g_wkval);
    cudaGetSymbolAddress((void**)&wkvbh,g_wkvbh); cudaGetSymbolAddress((void**)&wkvbl,g_wkvbl);
    cudaGetSymbolAddress((void**)&woh, g_woh);  cudaGetSymbolAddress((void**)&wol, g_wol);
    cudaGetSymbolAddress((void**)&cqh, g_cqh);  cudaGetSymbolAddress((void**)&cql, g_cql);
    cudaGetSymbolAddress((void**)&kvnh,g_kvnh); cudaGetSymbolAddress((void**)&kvnl,g_kvnl);
    cudaGetSymbolAddress((void**)&ah,  g_ah);   cudaGetSymbolAddress((void**)&al,  g_al);
    cudaGetSymbolAddress((void**)&qb,  g_qb);   cudaGetSymbolAddress((void**)&kb,  g_kb);
    cudaGetSymbolAddress((void**)&vh,  g_vhp);  cudaGetSymbolAddress((void**)&vl,  g_vlp);

    const int smem128 = STAGES * (16384 + 128*128);
    const int smem64  = STAGES * (16384 + 64*128);
    cudaFuncSetAttribute(gemm_bf16x3<128>, cudaFuncAttributeMaxDynamicSharedMemorySize, smem128);
    cudaFuncSetAttribute(gemm_bf16x3<64>,  cudaFuncAttributeMaxDynamicSharedMemorySize, smem64);
    cudaFuncSetAttribute(attn_mma, cudaFuncAttributeMaxDynamicSharedMemorySize, ATT_SMEM_BYTES);

    // 0) split operands to bf16 hi/lo planes
    split_pass(x,     xh,   xl,   (size_t)ROWS * NDIM);
    split_pass(wq_a,  wqah, wqal, (size_t)QRANK * NDIM);
    split_pass(wq_b,  wqbh, wqbl, (size_t)QDIM * QRANK);
    split_pass(wkv_a, wkvah,wkval,(size_t)CDIM * NDIM);
    split_pass(wkv_b, wkvbh,wkvbl,(size_t)KVDIM * KVRANK);
    split_pass(wo,    woh,  wol,  (size_t)NDIM * ODIM);

    // 1) cq = x @ wq_a^T
    gemm_bf16x3<128><<<dim3(QRANK/128, ROWS/128), 256, smem128>>>(xh, xl, wqah, wqal, cq, ROWS, QRANK, NDIM);
    // 2) rmsnorm(cq)
    rmsnorm_split_k<<<ROWS, 256>>>(cq, cqh, cql, qnw, QRANK, QRANK);
    // 3) q = cqn @ wq_b^T
    gemm_bf16x3<128><<<dim3(QDIM/128, ROWS/128), 256, smem128>>>(cqh, cql, wqbh, wqbl, q, ROWS, QDIM, QRANK);
    // 4) c = x @ wkv_a^T
    gemm_bf16x3<64><<<dim3(CDIM/64, ROWS/128), 256, smem64>>>(xh, xl, wkvah, wkval, c, ROWS, CDIM, NDIM);
    // 5) kvn = rmsnorm(c[:, :512])
    rmsnorm_split_k<<<ROWS, 256>>>(c, kvnh, kvnl, kvnw, KVRANK, CDIM);
    // 6) kv = kvn @ wkv_b^T
    gemm_bf16x3<128><<<dim3(KVDIM/128, ROWS/128), 256, smem128>>>(kvnh, kvnl, wkvbh, wkvbl, kv, ROWS, KVDIM, KVRANK);
    // 7) attention operand conversion (rope fused)
    qconv_k<<<(NH*ROWS*96 + 255)/256, 256>>>(q, fc, qb);
    kconv_k<<<(NH*ROWS*96 + 255)/256, 256>>>(kv, c, fc, kb);
    vconv_k<<<(NH*ROWS*64 + 255)/256, 256>>>(kv, vh, vl);
    // 8) tensor-core flash attention -> bf16 hi/lo planes
    attn_mma<<<dim3(SS/128, NH, BB), 256, ATT_SMEM_BYTES>>>(qb, kb, vh, vl, ah, al);
    // 9) out = attn @ wo^T
    gemm_bf16x3<128><<<dim3(NDIM/128, ROWS/128), 256, smem128>>>(ah, al, woh, wol, out, ROWS, NDIM, ODIM);
}

// round 7
// speedup vs baseline: 6.6516x; 2.1651x over previous
#include <cuda_runtime.h>
#include <cuda_bf16.h>
#include <cuda_fp16.h>
#include <math.h>
#include <stdint.h>

// ---------------- problem constants ----------------
#define BB     2
#define SS     2048
#define NDIM   2048
#define NH     16
#define QRANK  1536
#define KVRANK 512
#define ROPE_D 64
#define NOPE_D 128
#define VDIM   128
#define QKH    192           // NOPE + ROPE
#define ROWS   (BB*SS)       // 4096
#define KVDIM  (NH*(NOPE_D+VDIM))  // 4096
#define QDIM   (NH*QKH)      // 3072
#define CDIM   (KVRANK+ROPE_D) // 576
#define ODIM   (NH*VDIM)     // 2048

typedef __half fp16;

// ---------------- scratch (device globals; no allocs allowed) ----------------
__device__ float g_cq [ROWS*QRANK];
__device__ float g_q  [ROWS*QDIM];
__device__ float g_c  [ROWS*CDIM];
__device__ float g_kv [ROWS*KVDIM];
// fp16 operand planes
__device__ fp16 g_xf  [ROWS*NDIM];
__device__ fp16 g_wqaf[QRANK*NDIM];
__device__ fp16 g_wqbf[QDIM*QRANK];
__device__ fp16 g_wkvaf[CDIM*NDIM];
__device__ fp16 g_wkvbf[KVDIM*KVRANK];
__device__ fp16 g_wof [NDIM*ODIM];
__device__ fp16 g_cqf [ROWS*QRANK];
__device__ fp16 g_kvnf[ROWS*KVRANK];
__device__ fp16 g_af  [ROWS*ODIM];
// attention operands (head-major layouts)
__device__ fp16 g_qb [NH*ROWS*QKH];     // roped q
__device__ fp16 g_kb [NH*ROWS*QKH];     // k_nope | roped k_pe
__device__ fp16 g_vb [NH*ROWS*VDIM];    // v

// ---------------- helpers ----------------
__device__ __forceinline__ uint32_t packh2(float x, float y) {
    __half2 h = __floats2half2_rn(x, y);
    return *(uint32_t*)&h;
}

// fast exp2 on FMA pipe (x <= 0), rel err ~1e-6
__device__ __forceinline__ float fexp2(float x) {
    x = fmaxf(x, -126.f);
    float fl = floorf(x);
    float f = x - fl;
    float p = 1.535336188319500e-4f;
    p = fmaf(p, f, 1.339887440266574e-3f);
    p = fmaf(p, f, 9.618437357674640e-3f);
    p = fmaf(p, f, 5.550332471162809e-2f);
    p = fmaf(p, f, 2.402264791363012e-1f);
    p = fmaf(p, f, 6.931472028550421e-1f);
    p = fmaf(p, f, 1.0f);
    return p * __int_as_float(((int)fl + 127) << 23);
}

__global__ void cvt_fp16_k(const float4* __restrict__ in, uint2* __restrict__ out, int n4)
{
    int i = blockIdx.x * blockDim.x + threadIdx.x;
    if (i >= n4) return;
    float4 v = in[i];
    uint2 o;
    o.x = packh2(v.x, v.y);
    o.y = packh2(v.z, v.w);
    out[i] = o;
}

__device__ __forceinline__ uint32_t cvta_shared_u32(const void* p) {
    return (uint32_t)__cvta_generic_to_shared(p);
}

#define CP_ASYNC16(dst, src) \
    asm volatile("cp.async.cg.shared.global [%0], [%1], 16;" :: "r"(dst), "l"(src) : "memory")
#define CP_COMMIT() asm volatile("cp.async.commit_group;" ::: "memory")
#define CP_WAIT(N)  asm volatile("cp.async.wait_group %0;" :: "n"(N) : "memory")

#define LDSM_X4(r0,r1,r2,r3,addr) \
    asm volatile("ldmatrix.sync.aligned.m8n8.x4.shared.b16 {%0,%1,%2,%3}, [%4];" \
        : "=r"(r0), "=r"(r1), "=r"(r2), "=r"(r3) : "r"(addr))

#define LDSM_X4T(r0,r1,r2,r3,addr) \
    asm volatile("ldmatrix.sync.aligned.m8n8.x4.trans.shared.b16 {%0,%1,%2,%3}, [%4];" \
        : "=r"(r0), "=r"(r1), "=r"(r2), "=r"(r3) : "r"(addr))

#define MMA_F16(d, a, b) \
    asm volatile("mma.sync.aligned.m16n8k16.row.col.f32.f16.f16.f32 " \
        "{%0,%1,%2,%3}, {%4,%5,%6,%7}, {%8,%9}, {%0,%1,%2,%3};" \
        : "+f"((d)[0]), "+f"((d)[1]), "+f"((d)[2]), "+f"((d)[3]) \
        : "r"((a)[0]), "r"((a)[1]), "r"((a)[2]), "r"((a)[3]), "r"((b)[0]), "r"((b)[1]))

// ---------------- fp16 GEMM: C[M,N] = A[M,K] * B[N,K]^T (fp32 accum) ----------------
// CTA 128 x NT, K-chunk 64 (=128B fp16 row), XOR-8 swizzle, 4-stage cp.async ring.
// 8 warps: 2(M) x 4(N), warp tile 64 x NT/4.
#define STAGES 4

template<int NT>
__device__ __forceinline__ void load_stage(
    const fp16* __restrict__ A, const fp16* __restrict__ B,
    int K, int m0, int n0, int k0, uint32_t sA, int tid)
{
    constexpr int TOT = (128 + NT) * 8;
    #pragma unroll
    for (int i = 0; i < TOT / 256; i++) {
        int c = tid + i * 256;
        int row = c >> 3;
        int u = c & 7;               // 16B unit within 128B row
        if (row < 128) {
            const fp16* src = A + (size_t)(m0 + row) * K + k0 + u * 8;
            uint32_t dst = sA + row * 128 + ((u ^ (row & 7)) << 4);
            CP_ASYNC16(dst, src);
        } else {
            int br = row - 128;
            const fp16* src = B + (size_t)(n0 + br) * K + k0 + u * 8;
            uint32_t dst = sA + 16384 + br * 128 + ((u ^ (br & 7)) << 4);
            CP_ASYNC16(dst, src);
        }
    }
}

template<int NT>
__global__ __launch_bounds__(256, 1) void gemm_fp16(
    const fp16* __restrict__ A, const fp16* __restrict__ B,
    float* __restrict__ C, int M, int N, int K)
{
    constexpr int WN = NT / 4;
    constexpr int NI = WN / 8;
    constexpr int CHUNK = 16384 + NT * 128;

    extern __shared__ char smem_raw[];
    const uint32_t sbase = cvta_shared_u32(smem_raw);

    const int tid = threadIdx.x;
    const int wid = tid >> 5, lane = tid & 31;
    const int wm = wid >> 2, wn = wid & 3;
    const int m0 = blockIdx.y * 128;
    const int n0 = blockIdx.x * NT;
    const int mat = lane >> 3, r8 = lane & 7;

    float acc[4][NI][4];
    #pragma unroll
    for (int i = 0; i < 4; i++)
        #pragma unroll
        for (int j = 0; j < NI; j++)
            #pragma unroll
            for (int e = 0; e < 4; e++) acc[i][j][e] = 0.f;

    const int kT = K / 64;

    #pragma unroll
    for (int st = 0; st < STAGES - 1; st++) {
        load_stage<NT>(A, B, K, m0, n0, st * 64, sbase + st * CHUNK, tid);
        CP_COMMIT();
    }

    for (int it = 0; it < kT; it++) {
        CP_WAIT(STAGES - 2);
        __syncthreads();

        int nf = it + STAGES - 1;
        if (nf < kT)
            load_stage<NT>(A, B, K, m0, n0, nf * 64,
                           sbase + (nf % STAGES) * CHUNK, tid);
        CP_COMMIT();

        const uint32_t sA = sbase + (it % STAGES) * CHUNK;
        const uint32_t sB = sA + 16384;

        #pragma unroll
        for (int s = 0; s < 4; s++) {          // four k16 steps per 64-chunk
            const int kg = s * 2 + (mat >> 1);
            uint32_t a[4][4];
            uint32_t b[NI][2];

            #pragma unroll
            for (int mt = 0; mt < 4; mt++) {
                int row = wm * 64 + mt * 16 + (mat & 1) * 8 + r8;
                uint32_t rb = sA + row * 128;
                int x7 = row & 7;
                LDSM_X4(a[mt][0], a[mt][1], a[mt][2], a[mt][3],
                        rb + ((kg ^ x7) << 4));
            }
            #pragma unroll
            for (int p = 0; p < NI / 2; p++) {
                int row = wn * WN + p * 16 + (mat & 1) * 8 + r8;
                uint32_t rb = sB + row * 128;
                int x7 = row & 7;
                uint32_t t0, t1, t2, t3;
                LDSM_X4(t0, t1, t2, t3, rb + ((kg ^ x7) << 4));
                b[2*p][0] = t0; b[2*p][1] = t2;
                b[2*p+1][0] = t1; b[2*p+1][1] = t3;
            }

            #pragma unroll
            for (int mt = 0; mt < 4; mt++)
                #pragma unroll
                for (int nt = 0; nt < NI; nt++)
                    MMA_F16(acc[mt][nt], a[mt], b[nt]);
        }
    }

    const int qm = lane >> 2, qn = (lane & 3) * 2;
    #pragma unroll
    for (int mt = 0; mt < 4; mt++)
        #pragma unroll
        for (int nt = 0; nt < NI; nt++) {
            int m = m0 + wm * 64 + mt * 16 + qm;
            int n = n0 + wn * WN + nt * 8 + qn;
            *(float2*)&C[(size_t)m * N + n]       = make_float2(acc[mt][nt][0], acc[mt][nt][1]);
            *(float2*)&C[(size_t)(m + 8) * N + n] = make_float2(acc[mt][nt][2], acc[mt][nt][3]);
        }
}

// ---------------- RMSNorm -> fp16 plane ----------------
__global__ __launch_bounds__(256) void rmsnorm_cvt_k(
    const float* __restrict__ in, fp16* __restrict__ o,
    const float* __restrict__ w, int L, int sin)
{
    __shared__ float red[8];
    const int row = blockIdx.x;
    const float* ip = in + (size_t)row * sin;
    float ss = 0.f;
    for (int i = threadIdx.x; i < L; i += 256) {
        float v = ip[i];
        ss = fmaf(v, v, ss);
    }
    #pragma unroll
    for (int off = 16; off; off >>= 1)
        ss += __shfl_xor_sync(0xffffffffu, ss, off);
    if ((threadIdx.x & 31) == 0) red[threadIdx.x >> 5] = ss;
    __syncthreads();
    if (threadIdx.x == 0) {
        float tot = 0.f;
        #pragma unroll
        for (int i = 0; i < 8; i++) tot += red[i];
        red[0] = rsqrtf(tot / (float)L + 1e-6f);
    }
    __syncthreads();
    float inv = red[0];
    for (int i = threadIdx.x; i < L; i += 256)
        o[(size_t)row * L + i] = __float2half_rn(ip[i] * inv * w[i]);
}

// ---------------- attention operand conversion (rope fused) ----------------
__global__ void qconv_k(const float* __restrict__ q, const float* __restrict__ fc,
                        fp16* __restrict__ qb)
{
    int idx = blockIdx.x * blockDim.x + threadIdx.x;
    if (idx >= NH * ROWS * 96) return;
    int p = idx % 96;
    int rowh = idx / 96;
    int row = rowh & (ROWS - 1);
    int h = rowh >> 12;
    int s = row & (SS - 1);
    const float* src = q + (size_t)row * QDIM + h * QKH + 2 * p;
    float v0 = src[0], v1 = src[1];
    if (p >= 64) {
        int pp = p - 64;
        float cs = fc[(s * 32 + pp) * 2 + 0];
        float sn = fc[(s * 32 + pp) * 2 + 1];
        float r = v0 * cs - v1 * sn;
        float i2 = v0 * sn + v1 * cs;
        v0 = r; v1 = i2;
    }
    *(uint32_t*)(qb + ((size_t)h * ROWS + row) * QKH + 2 * p) = packh2(v0, v1);
}

__global__ void kconv_k(const float* __restrict__ kv, const float* __restrict__ c,
                        const float* __restrict__ fc, fp16* __restrict__ kb)
{
    int idx = blockIdx.x * blockDim.x + threadIdx.x;
    if (idx >= NH * ROWS * 96) return;
    int p = idx % 96;
    int rowh = idx / 96;
    int row = rowh & (ROWS - 1);
    int h = rowh >> 12;
    int s = row & (SS - 1);
    float v0, v1;
    if (p < 64) {
        const float* src = kv + (size_t)row * KVDIM + h * 256 + 2 * p;
        v0 = src[0]; v1 = src[1];
    } else {
        int pp = p - 64;
        const float* src = c + (size_t)row * CDIM + KVRANK + 2 * pp;
        float a = src[0], b = src[1];
        float cs = fc[(s * 32 + pp) * 2 + 0];
        float sn = fc[(s * 32 + pp) * 2 + 1];
        v0 = a * cs - b * sn;
        v1 = a * sn + b * cs;
    }
    *(uint32_t*)(kb + ((size_t)h * ROWS + row) * QKH + 2 * p) = packh2(v0, v1);
}

__global__ void vconv_k(const float* __restrict__ kv, fp16* __restrict__ vb)
{
    int idx = blockIdx.x * blockDim.x + threadIdx.x;
    if (idx >= NH * ROWS * 64) return;
    int p = idx & 63;
    int rowh = idx >> 6;
    int row = rowh & (ROWS - 1);
    int h = rowh >> 12;
    const float* src = kv + (size_t)row * KVDIM + h * 256 + 128 + 2 * p;
    size_t off = ((size_t)h * ROWS + row) * VDIM + 2 * p;
    *(uint32_t*)(vb + off) = packh2(src[0], src[1]);
}

// ---------------- tensor-core flash attention (fp16) ----------------
// q-tile 128 rows, 8 warps x m16; key tiles 64; D=192.
// smem (fp16 elems): Q 128x200, K[2] 64x200, V[2] 64x136.
#define ATT_SMEM_BYTES ((128*200 + 2*64*200 + 2*64*136) * 2)

__global__ __launch_bounds__(256, 1) void attn_mma(
    const fp16* __restrict__ gq, const fp16* __restrict__ gk,
    const fp16* __restrict__ gv, fp16* __restrict__ go)
{
    extern __shared__ fp16 asm_[];
    const uint32_t sQ = cvta_shared_u32(asm_);
    const uint32_t sK = sQ + 128 * 200 * 2;
    const uint32_t sV = sK + 2 * 64 * 200 * 2;

    const int tid = threadIdx.x;
    const int wid = tid >> 5, lane = tid & 31;
    const int qt = gridDim.x - 1 - blockIdx.x;
    const int q0 = qt * 128;
    const int h  = blockIdx.y;
    const int b  = blockIdx.z;
    const size_t hb = (size_t)h * ROWS + b * SS;

    {
        const fp16* qbase = gq + (hb + q0) * QKH;
        for (int i = tid; i < 3072; i += 256) {
            int row = i / 24, u = i - row * 24;
            CP_ASYNC16(sQ + (row * 200 + u * 8) * 2, qbase + row * QKH + u * 8);
        }
    }

    const int nT = q0 / 64 + 2;

    auto load_tile = [&](int n0, int buf) {
        const fp16* kbase = gk + (hb + n0) * QKH;
        uint32_t kd = sK + buf * (64 * 200 * 2);
        for (int i = tid; i < 1536; i += 256) {
            int row = i / 24, u = i - row * 24;
            CP_ASYNC16(kd + (row * 200 + u * 8) * 2, kbase + row * QKH + u * 8);
        }
        const fp16* vbase = gv + (hb + n0) * VDIM;
        uint32_t vd = sV + buf * (64 * 136 * 2);
        for (int i = tid; i < 1024; i += 256) {
            int row = i >> 4, u = i & 15;
            CP_ASYNC16(vd + (row * 136 + u * 8) * 2, vbase + row * VDIM + u * 8);
        }
    };

    load_tile(0, 0);
    CP_COMMIT();

    float out[16][4];
    #pragma unroll
    for (int f = 0; f < 16; f++)
        #pragma unroll
        for (int e = 0; e < 4; e++) out[f][e] = 0.f;
    float m0 = -1e30f, m1 = -1e30f, l0 = 0.f, l1 = 0.f;

    const int mat = lane >> 3, r8 = lane & 7;
    const uint32_t aQ = sQ + ((wid * 16 + (lane & 15)) * 200 + (lane >> 4) * 8) * 2;
    const float sc2 = 0.07216878364870323f * 1.4426950408889634f;
    const int growA = q0 + wid * 16 + (lane >> 2);

    for (int t = 0; t < nT; t++) {
        const int buf = t & 1;
        if (t + 1 < nT) load_tile(64 * (t + 1), buf ^ 1);
        CP_COMMIT();
        CP_WAIT(1);
        __syncthreads();

        const int n0 = 64 * t;
        const bool active = (n0 <= q0 + wid * 16 + 15);
        if (active) {
            // ---- S = Q @ K^T ----
            float s[8][4];
            #pragma unroll
            for (int f = 0; f < 8; f++)
                #pragma unroll
                for (int e = 0; e < 4; e++) s[f][e] = 0.f;

            const uint32_t kB = sK + buf * (64 * 200 * 2)
                              + (((mat >> 1) * 8 + r8) * 200 + (mat & 1) * 8) * 2;
            #pragma unroll
            for (int kt = 0; kt < 12; kt++) {
                uint32_t a[4];
                LDSM_X4(a[0], a[1], a[2], a[3], aQ + kt * 32);
                #pragma unroll
                for (int g = 0; g < 4; g++) {
                    uint32_t b0, b1, b2, b3;
                    LDSM_X4(b0, b1, b2, b3, kB + (g * 16 * 200) * 2 + kt * 32);
                    uint32_t bb0[2] = {b0, b1}, bb1[2] = {b2, b3};
                    MMA_F16(s[2*g],   a, bb0);
                    MMA_F16(s[2*g+1], a, bb1);
                }
            }

            // ---- online softmax (log2 domain) ----
            const bool needmask = (n0 + 63 > q0 + wid * 16);
            const int colb = n0 + 2 * (lane & 3);
            float rm0 = -1e30f, rm1 = -1e30f;
            #pragma unroll
            for (int f = 0; f < 8; f++) {
                #pragma unroll
                for (int j = 0; j < 2; j++) {
                    int col = colb + f * 8 + j;
                    float z0 = s[f][j]     * sc2;
                    float z1 = s[f][2 + j] * sc2;
                    if (needmask) {
                        if (col > growA)     z0 = -1e30f;
                        if (col > growA + 8) z1 = -1e30f;
                    }
                    s[f][j] = z0; s[f][2 + j] = z1;
                    rm0 = fmaxf(rm0, z0); rm1 = fmaxf(rm1, z1);
                }
            }
            rm0 = fmaxf(rm0, __shfl_xor_sync(0xffffffffu, rm0, 1));
            rm0 = fmaxf(rm0, __shfl_xor_sync(0xffffffffu, rm0, 2));
            rm1 = fmaxf(rm1, __shfl_xor_sync(0xffffffffu, rm1, 1));
            rm1 = fmaxf(rm1, __shfl_xor_sync(0xffffffffu, rm1, 2));
            float mn0 = fmaxf(m0, rm0), mn1 = fmaxf(m1, rm1);
            float al0 = fexp2(m0 - mn0), al1 = fexp2(m1 - mn1);
            m0 = mn0; m1 = mn1;

            float rs0 = 0.f, rs1 = 0.f;
            #pragma unroll
            for (int f = 0; f < 8; f++) {
                #pragma unroll
                for (int j = 0; j < 2; j++) {
                    float p0 = fexp2(s[f][j]     - mn0);
                    float p1 = fexp2(s[f][2 + j] - mn1);
                    s[f][j] = p0; s[f][2 + j] = p1;
                    rs0 += p0; rs1 += p1;
                }
            }
            rs0 += __shfl_xor_sync(0xffffffffu, rs0, 1);
            rs0 += __shfl_xor_sync(0xffffffffu, rs0, 2);
            rs1 += __shfl_xor_sync(0xffffffffu, rs1, 1);
            rs1 += __shfl_xor_sync(0xffffffffu, rs1, 2);
            l0 = l0 * al0 + rs0;
            l1 = l1 * al1 + rs1;

            #pragma unroll
            for (int f = 0; f < 16; f++) {
                out[f][0] *= al0; out[f][1] *= al0;
                out[f][2] *= al1; out[f][3] *= al1;
            }

            // ---- O += P @ V (fp16) ----
            const uint32_t vB = sV + buf * (64 * 136 * 2)
                              + (((mat & 1) * 8 + r8) * 136 + (mat >> 1) * 8) * 2;
            #pragma unroll
            for (int kt = 0; kt < 4; kt++) {
                uint32_t pa[4];
                pa[0] = packh2(s[2*kt][0],   s[2*kt][1]);
                pa[1] = packh2(s[2*kt][2],   s[2*kt][3]);
                pa[2] = packh2(s[2*kt+1][0], s[2*kt+1][1]);
                pa[3] = packh2(s[2*kt+1][2], s[2*kt+1][3]);
                const uint32_t rowOff = (kt * 16 * 136) * 2;
                #pragma unroll
                for (int gv = 0; gv < 8; gv++) {
                    uint32_t h0, h1, h2, h3;
                    LDSM_X4T(h0, h1, h2, h3, vB + rowOff + gv * 32);
                    uint32_t bh0[2] = {h0, h1}, bh1[2] = {h2, h3};
                    MMA_F16(out[2*gv],   pa, bh0);
                    MMA_F16(out[2*gv+1], pa, bh1);
                }
            }
        }
        __syncthreads();
    }

    // ---- finalize ----
    float inv0 = 1.f / l0, inv1 = 1.f / l1;
    size_t r0g = (size_t)(b * SS + q0 + wid * 16 + (lane >> 2));
    size_t base0 = r0g * ODIM + h * VDIM + 2 * (lane & 3);
    size_t base1 = base0 + 8 * (size_t)ODIM;
    #pragma unroll
    for (int f = 0; f < 16; f++) {
        *(uint32_t*)&go[base0 + f * 8] = packh2(out[f][0] * inv0, out[f][1] * inv0);
        *(uint32_t*)&go[base1 + f * 8] = packh2(out[f][2] * inv1, out[f][3] * inv1);
    }
}

// ---------------- launcher ----------------
static inline void cvt_pass(const float* src, fp16* dst, size_t n)
{
    int n4 = (int)(n / 4);
    cvt_fp16_k<<<(n4 + 255) / 256, 256>>>((const float4*)src, (uint2*)dst, n4);
}

extern "C" void kernel_launch(void* const* d_in, const int* in_sizes, int n_in,
                              void* d_out, int out_size)
{
    const float* x     = (const float*)d_in[0];
    const float* fc    = (const float*)d_in[1];
    const float* wq_a  = (const float*)d_in[2];
    const float* qnw   = (const float*)d_in[3];
    const float* wq_b  = (const float*)d_in[4];
    const float* wkv_a = (const float*)d_in[5];
    const float* kvnw  = (const float*)d_in[6];
    const float* wkv_b = (const float*)d_in[7];
    const float* wo    = (const float*)d_in[8];
    float* out = (float*)d_out;

    float *cq, *q, *c, *kv;
    fp16 *xf, *wqaf, *wqbf, *wkvaf, *wkvbf, *wof, *cqf, *kvnf, *af, *qb, *kb, *vb;
    cudaGetSymbolAddress((void**)&cq,   g_cq);
    cudaGetSymbolAddress((void**)&q,    g_q);
    cudaGetSymbolAddress((void**)&c,    g_c);
    cudaGetSymbolAddress((void**)&kv,   g_kv);
    cudaGetSymbolAddress((void**)&xf,   g_xf);
    cudaGetSymbolAddress((void**)&wqaf, g_wqaf);
    cudaGetSymbolAddress((void**)&wqbf, g_wqbf);
    cudaGetSymbolAddress((void**)&wkvaf,g_wkvaf);
    cudaGetSymbolAddress((void**)&wkvbf,g_wkvbf);
    cudaGetSymbolAddress((void**)&wof,  g_wof);
    cudaGetSymbolAddress((void**)&cqf,  g_cqf);
    cudaGetSymbolAddress((void**)&kvnf, g_kvnf);
    cudaGetSymbolAddress((void**)&af,   g_af);
    cudaGetSymbolAddress((void**)&qb,   g_qb);
    cudaGetSymbolAddress((void**)&kb,   g_kb);
    cudaGetSymbolAddress((void**)&vb,   g_vb);

    const int smem128 = STAGES * (16384 + 128*128); // 131072
    const int smem64  = STAGES * (16384 + 64*128);  // 98304
    cudaFuncSetAttribute(gemm_fp16<128>, cudaFuncAttributeMaxDynamicSharedMemorySize, smem128);
    cudaFuncSetAttribute(gemm_fp16<64>,  cudaFuncAttributeMaxDynamicSharedMemorySize, smem64);
    cudaFuncSetAttribute(attn_mma, cudaFuncAttributeMaxDynamicSharedMemorySize, ATT_SMEM_BYTES);

    // 0) convert operands to fp16
    cvt_pass(x,     xf,   (size_t)ROWS * NDIM);
    cvt_pass(wq_a,  wqaf, (size_t)QRANK * NDIM);
    cvt_pass(wq_b,  wqbf, (size_t)QDIM * QRANK);
    cvt_pass(wkv_a, wkvaf,(size_t)CDIM * NDIM);
    cvt_pass(wkv_b, wkvbf,(size_t)KVDIM * KVRANK);
    cvt_pass(wo,    wof,  (size_t)NDIM * ODIM);

    // 1) cq = x @ wq_a^T
    gemm_fp16<128><<<dim3(QRANK/128, ROWS/128), 256, smem128>>>(xf, wqaf, cq, ROWS, QRANK, NDIM);
    // 2) rmsnorm(cq) -> fp16
    rmsnorm_cvt_k<<<ROWS, 256>>>(cq, cqf, qnw, QRANK, QRANK);
    // 3) q = cqn @ wq_b^T
    gemm_fp16<128><<<dim3(QDIM/128, ROWS/128), 256, smem128>>>(cqf, wqbf, q, ROWS, QDIM, QRANK);
    // 4) c = x @ wkv_a^T
    gemm_fp16<64><<<dim3(CDIM/64, ROWS/128), 256, smem64>>>(xf, wkvaf, c, ROWS, CDIM, NDIM);
    // 5) kvn = rmsnorm(c[:, :512]) -> fp16
    rmsnorm_cvt_k<<<ROWS, 256>>>(c, kvnf, kvnw, KVRANK, CDIM);
    // 6) kv = kvn @ wkv_b^T
    gemm_fp16<128><<<dim3(KVDIM/128, ROWS/128), 256, smem128>>>(kvnf, wkvbf, kv, ROWS, KVDIM, KVRANK);
    // 7) attention operand conversion (rope fused)
    qconv_k<<<(NH*ROWS*96 + 255)/256, 256>>>(q, fc, qb);
    kconv_k<<<(NH*ROWS*96 + 255)/256, 256>>>(kv, c, fc, kb);
    vconv_k<<<(NH*ROWS*64 + 255)/256, 256>>>(kv, vb);
    // 8) tensor-core flash attention -> fp16
    attn_mma<<<dim3(SS/128, NH, BB), 256, ATT_SMEM_BYTES>>>(qb, kb, vb, af);
    // 9) out = attn @ wo^T
    gemm_fp16<128><<<dim3(NDIM/128, ROWS/128), 256, smem128>>>(af, wof, out, ROWS, NDIM, ODIM);
}

// round 8
// speedup vs baseline: 7.0171x; 1.0549x over previous
#include <cuda_runtime.h>
#include <cuda_bf16.h>
#include <cuda_fp16.h>
#include <math.h>
#include <stdint.h>

// ---------------- problem constants ----------------
#define BB     2
#define SS     2048
#define NDIM   2048
#define NH     16
#define QRANK  1536
#define KVRANK 512
#define ROPE_D 64
#define NOPE_D 128
#define VDIM   128
#define QKH    192           // NOPE + ROPE
#define ROWS   (BB*SS)       // 4096
#define KVDIM  (NH*(NOPE_D+VDIM))  // 4096
#define QDIM   (NH*QKH)      // 3072
#define CDIM   (KVRANK+ROPE_D) // 576
#define ODIM   (NH*VDIM)     // 2048

typedef __half fp16;

// ---------------- scratch (device globals; no allocs allowed) ----------------
__device__ float g_cq [ROWS*QRANK];
__device__ float g_c  [ROWS*CDIM];
// fp16 operand planes
__device__ fp16 g_xf  [ROWS*NDIM];
__device__ fp16 g_wqaf[QRANK*NDIM];
__device__ fp16 g_wqbf[QDIM*QRANK];
__device__ fp16 g_wkvaf[CDIM*NDIM];
__device__ fp16 g_wkvbf[KVDIM*KVRANK];
__device__ fp16 g_wof [NDIM*ODIM];
__device__ fp16 g_cqf [ROWS*QRANK];
__device__ fp16 g_kvnf[ROWS*KVRANK];
__device__ fp16 g_af  [ROWS*ODIM];
// attention operands (head-major layouts)
__device__ fp16 g_qb [NH*ROWS*QKH];     // roped q
__device__ fp16 g_kb [NH*ROWS*QKH];     // k_nope | roped k_pe
__device__ fp16 g_vb [NH*ROWS*VDIM];    // v

// ---------------- helpers ----------------
__device__ __forceinline__ uint32_t packh2(float x, float y) {
    __half2 h = __floats2half2_rn(x, y);
    return *(uint32_t*)&h;
}

// fast exp2 on FMA pipe (x <= 0), rel err ~1e-6
__device__ __forceinline__ float fexp2(float x) {
    x = fmaxf(x, -126.f);
    float fl = floorf(x);
    float f = x - fl;
    float p = 1.535336188319500e-4f;
    p = fmaf(p, f, 1.339887440266574e-3f);
    p = fmaf(p, f, 9.618437357674640e-3f);
    p = fmaf(p, f, 5.550332471162809e-2f);
    p = fmaf(p, f, 2.402264791363012e-1f);
    p = fmaf(p, f, 6.931472028550421e-1f);
    p = fmaf(p, f, 1.0f);
    return p * __int_as_float(((int)fl + 127) << 23);
}

__global__ void cvt_fp16_k(const float4* __restrict__ in, uint2* __restrict__ out, int n4)
{
    int i = blockIdx.x * blockDim.x + threadIdx.x;
    if (i >= n4) return;
    float4 v = in[i];
    uint2 o;
    o.x = packh2(v.x, v.y);
    o.y = packh2(v.z, v.w);
    out[i] = o;
}

__device__ __forceinline__ uint32_t cvta_shared_u32(const void* p) {
    return (uint32_t)__cvta_generic_to_shared(p);
}

#define CP_ASYNC16(dst, src) \
    asm volatile("cp.async.cg.shared.global [%0], [%1], 16;" :: "r"(dst), "l"(src) : "memory")
#define CP_COMMIT() asm volatile("cp.async.commit_group;" ::: "memory")
#define CP_WAIT(N)  asm volatile("cp.async.wait_group %0;" :: "n"(N) : "memory")

#define LDSM_X4(r0,r1,r2,r3,addr) \
    asm volatile("ldmatrix.sync.aligned.m8n8.x4.shared.b16 {%0,%1,%2,%3}, [%4];" \
        : "=r"(r0), "=r"(r1), "=r"(r2), "=r"(r3) : "r"(addr))

#define LDSM_X4T(r0,r1,r2,r3,addr) \
    asm volatile("ldmatrix.sync.aligned.m8n8.x4.trans.shared.b16 {%0,%1,%2,%3}, [%4];" \
        : "=r"(r0), "=r"(r1), "=r"(r2), "=r"(r3) : "r"(addr))

#define MMA_F16(d, a, b) \
    asm volatile("mma.sync.aligned.m16n8k16.row.col.f32.f16.f16.f32 " \
        "{%0,%1,%2,%3}, {%4,%5,%6,%7}, {%8,%9}, {%0,%1,%2,%3};" \
        : "+f"((d)[0]), "+f"((d)[1]), "+f"((d)[2]), "+f"((d)[3]) \
        : "r"((a)[0]), "r"((a)[1]), "r"((a)[2]), "r"((a)[3]), "r"((b)[0]), "r"((b)[1]))

// ---------------- fp16 GEMM: C[M,N] = A[M,K] * B[N,K]^T (fp32 accum) ----------------
// CTA 128 x NT, K-chunk 64 (=128B fp16 row), XOR-8 swizzle, 4-stage cp.async ring.
// 8 warps: 2(M) x 4(N), warp tile 64 x NT/4.
// MODE 0: write fp32 C. MODE 1: rope + fp16 head-major qb. MODE 2: fp16 kb/vb scatter.
#define STAGES 4

template<int NT>
__device__ __forceinline__ void load_stage(
    const fp16* __restrict__ A, const fp16* __restrict__ B,
    int K, int m0, int n0, int k0, uint32_t sA, int tid)
{
    constexpr int TOT = (128 + NT) * 8;
    #pragma unroll
    for (int i = 0; i < TOT / 256; i++) {
        int c = tid + i * 256;
        int row = c >> 3;
        int u = c & 7;               // 16B unit within 128B row
        if (row < 128) {
            const fp16* src = A + (size_t)(m0 + row) * K + k0 + u * 8;
            uint32_t dst = sA + row * 128 + ((u ^ (row & 7)) << 4);
            CP_ASYNC16(dst, src);
        } else {
            int br = row - 128;
            const fp16* src = B + (size_t)(n0 + br) * K + k0 + u * 8;
            uint32_t dst = sA + 16384 + br * 128 + ((u ^ (br & 7)) << 4);
            CP_ASYNC16(dst, src);
        }
    }
}

template<int NT, int MODE>
__global__ __launch_bounds__(256, 1) void gemm_fp16(
    const fp16* __restrict__ A, const fp16* __restrict__ B,
    float* __restrict__ C, fp16* __restrict__ O1, fp16* __restrict__ O2,
    const float* __restrict__ fc, int M, int N, int K)
{
    constexpr int WN = NT / 4;
    constexpr int NI = WN / 8;
    constexpr int CHUNK = 16384 + NT * 128;

    extern __shared__ char smem_raw[];
    const uint32_t sbase = cvta_shared_u32(smem_raw);

    const int tid = threadIdx.x;
    const int wid = tid >> 5, lane = tid & 31;
    const int wm = wid >> 2, wn = wid & 3;
    const int m0 = blockIdx.y * 128;
    const int n0 = blockIdx.x * NT;
    const int mat = lane >> 3, r8 = lane & 7;

    float acc[4][NI][4];
    #pragma unroll
    for (int i = 0; i < 4; i++)
        #pragma unroll
        for (int j = 0; j < NI; j++)
            #pragma unroll
            for (int e = 0; e < 4; e++) acc[i][j][e] = 0.f;

    const int kT = K / 64;

    #pragma unroll
    for (int st = 0; st < STAGES - 1; st++) {
        load_stage<NT>(A, B, K, m0, n0, st * 64, sbase + st * CHUNK, tid);
        CP_COMMIT();
    }

    for (int it = 0; it < kT; it++) {
        CP_WAIT(STAGES - 2);
        __syncthreads();

        int nf = it + STAGES - 1;
        if (nf < kT)
            load_stage<NT>(A, B, K, m0, n0, nf * 64,
                           sbase + (nf % STAGES) * CHUNK, tid);
        CP_COMMIT();

        const uint32_t sA = sbase + (it % STAGES) * CHUNK;
        const uint32_t sB = sA + 16384;

        #pragma unroll
        for (int s = 0; s < 4; s++) {          // four k16 steps per 64-chunk
            const int kg = s * 2 + (mat >> 1);
            uint32_t a[4][4];
            uint32_t b[NI][2];

            #pragma unroll
            for (int mt = 0; mt < 4; mt++) {
                int row = wm * 64 + mt * 16 + (mat & 1) * 8 + r8;
                uint32_t rb = sA + row * 128;
                int x7 = row & 7;
                LDSM_X4(a[mt][0], a[mt][1], a[mt][2], a[mt][3],
                        rb + ((kg ^ x7) << 4));
            }
            #pragma unroll
            for (int p = 0; p < NI / 2; p++) {
                int row = wn * WN + p * 16 + (mat & 1) * 8 + r8;
                uint32_t rb = sB + row * 128;
                int x7 = row & 7;
                uint32_t t0, t1, t2, t3;
                LDSM_X4(t0, t1, t2, t3, rb + ((kg ^ x7) << 4));
                b[2*p][0] = t0; b[2*p][1] = t2;
                b[2*p+1][0] = t1; b[2*p+1][1] = t3;
            }

            #pragma unroll
            for (int mt = 0; mt < 4; mt++)
                #pragma unroll
                for (int nt = 0; nt < NI; nt++)
                    MMA_F16(acc[mt][nt], a[mt], b[nt]);
        }
    }

    const int qm = lane >> 2, qn = (lane & 3) * 2;
    #pragma unroll
    for (int mt = 0; mt < 4; mt++)
        #pragma unroll
        for (int nt = 0; nt < NI; nt++) {
            int m = m0 + wm * 64 + mt * 16 + qm;     // rows m, m+8
            int n = n0 + wn * WN + nt * 8 + qn;      // cols n, n+1 (n even)
            float v0 = acc[mt][nt][0], v1 = acc[mt][nt][1];
            float v2 = acc[mt][nt][2], v3 = acc[mt][nt][3];
            if (MODE == 0) {
                *(float2*)&C[(size_t)m * N + n]       = make_float2(v0, v1);
                *(float2*)&C[(size_t)(m + 8) * N + n] = make_float2(v2, v3);
            } else if (MODE == 1) {
                // q: rope on pe pairs, fp16 head-major
                int h = n / QKH, p2 = n % QKH;
                if (p2 >= NOPE_D) {
                    int pp = (p2 - NOPE_D) >> 1;
                    int s0 = m & (SS - 1), s8 = (m + 8) & (SS - 1);
                    float cs0 = fc[(s0 * 32 + pp) * 2], sn0 = fc[(s0 * 32 + pp) * 2 + 1];
                    float cs8 = fc[(s8 * 32 + pp) * 2], sn8 = fc[(s8 * 32 + pp) * 2 + 1];
                    float r0 = v0 * cs0 - v1 * sn0, i0 = v0 * sn0 + v1 * cs0;
                    float r2 = v2 * cs8 - v3 * sn8, i2 = v2 * sn8 + v3 * cs8;
                    v0 = r0; v1 = i0; v2 = r2; v3 = i2;
                }
                fp16* dst = O1 + ((size_t)h * ROWS + m) * QKH + p2;
                *(uint32_t*)dst               = packh2(v0, v1);
                *(uint32_t*)(dst + 8 * QKH)   = packh2(v2, v3);
            } else {
                // kv: scatter k_nope -> O1 (kb), v -> O2 (vb)
                int h = n >> 8, c2 = n & 255;
                if (c2 < NOPE_D) {
                    fp16* dst = O1 + ((size_t)h * ROWS + m) * QKH + c2;
                    *(uint32_t*)dst             = packh2(v0, v1);
                    *(uint32_t*)(dst + 8 * QKH) = packh2(v2, v3);
                } else {
                    fp16* dst = O2 + ((size_t)h * ROWS + m) * VDIM + (c2 - NOPE_D);
                    *(uint32_t*)dst              = packh2(v0, v1);
                    *(uint32_t*)(dst + 8 * VDIM) = packh2(v2, v3);
                }
            }
        }
}

// ---------------- RMSNorm -> fp16 plane ----------------
__global__ __launch_bounds__(256) void rmsnorm_cvt_k(
    const float* __restrict__ in, fp16* __restrict__ o,
    const float* __restrict__ w, int L, int sin)
{
    __shared__ float red[8];
    const int row = blockIdx.x;
    const float* ip = in + (size_t)row * sin;
    float ss = 0.f;
    for (int i = threadIdx.x; i < L; i += 256) {
        float v = ip[i];
        ss = fmaf(v, v, ss);
    }
    #pragma unroll
    for (int off = 16; off; off >>= 1)
        ss += __shfl_xor_sync(0xffffffffu, ss, off);
    if ((threadIdx.x & 31) == 0) red[threadIdx.x >> 5] = ss;
    __syncthreads();
    if (threadIdx.x == 0) {
        float tot = 0.f;
        #pragma unroll
        for (int i = 0; i < 8; i++) tot += red[i];
        red[0] = rsqrtf(tot / (float)L + 1e-6f);
    }
    __syncthreads();
    float inv = red[0];
    for (int i = threadIdx.x; i < L; i += 256)
        o[(size_t)row * L + i] = __float2half_rn(ip[i] * inv * w[i]);
}

// ---------------- k_pe conversion (rope; shared across heads) ----------------
__global__ void kpe_conv_k(const float* __restrict__ c, const float* __restrict__ fc,
                           fp16* __restrict__ kb)
{
    int idx = blockIdx.x * blockDim.x + threadIdx.x;
    if (idx >= NH * ROWS * 32) return;
    int p = idx & 31;
    int rowh = idx >> 5;
    int row = rowh & (ROWS - 1);
    int h = rowh >> 12;
    int s = row & (SS - 1);
    const float* src = c + (size_t)row * CDIM + KVRANK + 2 * p;
    float a = src[0], b = src[1];
    float cs = fc[(s * 32 + p) * 2 + 0];
    float sn = fc[(s * 32 + p) * 2 + 1];
    float v0 = a * cs - b * sn;
    float v1 = a * sn + b * cs;
    *(uint32_t*)(kb + ((size_t)h * ROWS + row) * QKH + NOPE_D + 2 * p) = packh2(v0, v1);
}

// ---------------- tensor-core flash attention (fp16) ----------------
// q-tile 128 rows, 8 warps x m16; key tiles 64; D=192.
// smem (fp16 elems): Q 128x200, K[2] 64x200, V[2] 64x136.
#define ATT_SMEM_BYTES ((128*200 + 2*64*200 + 2*64*136) * 2)

__global__ __launch_bounds__(256, 1) void attn_mma(
    const fp16* __restrict__ gq, const fp16* __restrict__ gk,
    const fp16* __restrict__ gv, fp16* __restrict__ go)
{
    extern __shared__ fp16 asm_[];
    const uint32_t sQ = cvta_shared_u32(asm_);
    const uint32_t sK = sQ + 128 * 200 * 2;
    const uint32_t sV = sK + 2 * 64 * 200 * 2;

    const int tid = threadIdx.x;
    const int wid = tid >> 5, lane = tid & 31;
    const int qt = gridDim.x - 1 - blockIdx.x;
    const int q0 = qt * 128;
    const int h  = blockIdx.y;
    const int b  = blockIdx.z;
    const size_t hb = (size_t)h * ROWS + b * SS;

    {
        const fp16* qbase = gq + (hb + q0) * QKH;
        for (int i = tid; i < 3072; i += 256) {
            int row = i / 24, u = i - row * 24;
            CP_ASYNC16(sQ + (row * 200 + u * 8) * 2, qbase + row * QKH + u * 8);
        }
    }

    const int nT = q0 / 64 + 2;

    auto load_tile = [&](int n0, int buf) {
        const fp16* kbase = gk + (hb + n0) * QKH;
        uint32_t kd = sK + buf * (64 * 200 * 2);
        for (int i = tid; i < 1536; i += 256) {
            int row = i / 24, u = i - row * 24;
            CP_ASYNC16(kd + (row * 200 + u * 8) * 2, kbase + row * QKH + u * 8);
        }
        const fp16* vbase = gv + (hb + n0) * VDIM;
        uint32_t vd = sV + buf * (64 * 136 * 2);
        for (int i = tid; i < 1024; i += 256) {
            int row = i >> 4, u = i & 15;
            CP_ASYNC16(vd + (row * 136 + u * 8) * 2, vbase + row * VDIM + u * 8);
        }
    };

    load_tile(0, 0);
    CP_COMMIT();

    float out[16][4];
    #pragma unroll
    for (int f = 0; f < 16; f++)
        #pragma unroll
        for (int e = 0; e < 4; e++) out[f][e] = 0.f;
    float m0 = -1e30f, m1 = -1e30f, l0 = 0.f, l1 = 0.f;

    const int mat = lane >> 3, r8 = lane & 7;
    const uint32_t aQ = sQ + ((wid * 16 + (lane & 15)) * 200 + (lane >> 4) * 8) * 2;
    const float sc2 = 0.07216878364870323f * 1.4426950408889634f;
    const int growA = q0 + wid * 16 + (lane >> 2);

    for (int t = 0; t < nT; t++) {
        const int buf = t & 1;
        if (t + 1 < nT) load_tile(64 * (t + 1), buf ^ 1);
        CP_COMMIT();
        CP_WAIT(1);
        __syncthreads();

        const int n0 = 64 * t;
        const bool active = (n0 <= q0 + wid * 16 + 15);
        if (active) {
            // ---- S = Q @ K^T ----
            float s[8][4];
            #pragma unroll
            for (int f = 0; f < 8; f++)
                #pragma unroll
                for (int e = 0; e < 4; e++) s[f][e] = 0.f;

            const uint32_t kB = sK + buf * (64 * 200 * 2)
                              + (((mat >> 1) * 8 + r8) * 200 + (mat & 1) * 8) * 2;
            #pragma unroll
            for (int kt = 0; kt < 12; kt++) {
                uint32_t a[4];
                LDSM_X4(a[0], a[1], a[2], a[3], aQ + kt * 32);
                #pragma unroll
                for (int g = 0; g < 4; g++) {
                    uint32_t b0, b1, b2, b3;
                    LDSM_X4(b0, b1, b2, b3, kB + (g * 16 * 200) * 2 + kt * 32);
                    uint32_t bb0[2] = {b0, b1}, bb1[2] = {b2, b3};
                    MMA_F16(s[2*g],   a, bb0);
                    MMA_F16(s[2*g+1], a, bb1);
                }
            }

            // ---- online softmax (log2 domain) ----
            const bool needmask = (n0 + 63 > q0 + wid * 16);
            const int colb = n0 + 2 * (lane & 3);
            float rm0 = -1e30f, rm1 = -1e30f;
            #pragma unroll
            for (int f = 0; f < 8; f++) {
                #pragma unroll
                for (int j = 0; j < 2; j++) {
                    int col = colb + f * 8 + j;
                    float z0 = s[f][j]     * sc2;
                    float z1 = s[f][2 + j] * sc2;
                    if (needmask) {
                        if (col > growA)     z0 = -1e30f;
                        if (col > growA + 8) z1 = -1e30f;
                    }
                    s[f][j] = z0; s[f][2 + j] = z1;
                    rm0 = fmaxf(rm0, z0); rm1 = fmaxf(rm1, z1);
                }
            }
            rm0 = fmaxf(rm0, __shfl_xor_sync(0xffffffffu, rm0, 1));
            rm0 = fmaxf(rm0, __shfl_xor_sync(0xffffffffu, rm0, 2));
            rm1 = fmaxf(rm1, __shfl_xor_sync(0xffffffffu, rm1, 1));
            rm1 = fmaxf(rm1, __shfl_xor_sync(0xffffffffu, rm1, 2));
            float mn0 = fmaxf(m0, rm0), mn1 = fmaxf(m1, rm1);
            float al0 = fexp2(m0 - mn0), al1 = fexp2(m1 - mn1);
            m0 = mn0; m1 = mn1;

            float rs0 = 0.f, rs1 = 0.f;
            #pragma unroll
            for (int f = 0; f < 8; f++) {
                #pragma unroll
                for (int j = 0; j < 2; j++) {
                    float p0 = fexp2(s[f][j]     - mn0);
                    float p1 = fexp2(s[f][2 + j] - mn1);
                    s[f][j] = p0; s[f][2 + j] = p1;
                    rs0 += p0; rs1 += p1;
                }
            }
            rs0 += __shfl_xor_sync(0xffffffffu, rs0, 1);
            rs0 += __shfl_xor_sync(0xffffffffu, rs0, 2);
            rs1 += __shfl_xor_sync(0xffffffffu, rs1, 1);
            rs1 += __shfl_xor_sync(0xffffffffu, rs1, 2);
            l0 = l0 * al0 + rs0;
            l1 = l1 * al1 + rs1;

            #pragma unroll
            for (int f = 0; f < 16; f++) {
                out[f][0] *= al0; out[f][1] *= al0;
                out[f][2] *= al1; out[f][3] *= al1;
            }

            // ---- O += P @ V (fp16) ----
            const uint32_t vB = sV + buf * (64 * 136 * 2)
                              + (((mat & 1) * 8 + r8) * 136 + (mat >> 1) * 8) * 2;
            #pragma unroll
            for (int kt = 0; kt < 4; kt++) {
                uint32_t pa[4];
                pa[0] = packh2(s[2*kt][0],   s[2*kt][1]);
                pa[1] = packh2(s[2*kt][2],   s[2*kt][3]);
                pa[2] = packh2(s[2*kt+1][0], s[2*kt+1][1]);
                pa[3] = packh2(s[2*kt+1][2], s[2*kt+1][3]);
                const uint32_t rowOff = (kt * 16 * 136) * 2;
                #pragma unroll
                for (int gv = 0; gv < 8; gv++) {
                    uint32_t h0, h1, h2, h3;
                    LDSM_X4T(h0, h1, h2, h3, vB + rowOff + gv * 32);
                    uint32_t bh0[2] = {h0, h1}, bh1[2] = {h2, h3};
                    MMA_F16(out[2*gv],   pa, bh0);
                    MMA_F16(out[2*gv+1], pa, bh1);
                }
            }
        }
        __syncthreads();
    }

    // ---- finalize ----
    float inv0 = 1.f / l0, inv1 = 1.f / l1;
    size_t r0g = (size_t)(b * SS + q0 + wid * 16 + (lane >> 2));
    size_t base0 = r0g * ODIM + h * VDIM + 2 * (lane & 3);
    size_t base1 = base0 + 8 * (size_t)ODIM;
    #pragma unroll
    for (int f = 0; f < 16; f++) {
        *(uint32_t*)&go[base0 + f * 8] = packh2(out[f][0] * inv0, out[f][1] * inv0);
        *(uint32_t*)&go[base1 + f * 8] = packh2(out[f][2] * inv1, out[f][3] * inv1);
    }
}

// ---------------- launcher ----------------
static inline void cvt_pass(const float* src, fp16* dst, size_t n)
{
    int n4 = (int)(n / 4);
    cvt_fp16_k<<<(n4 + 255) / 256, 256>>>((const float4*)src, (uint2*)dst, n4);
}

extern "C" void kernel_launch(void* const* d_in, const int* in_sizes, int n_in,
                              void* d_out, int out_size)
{
    const float* x     = (const float*)d_in[0];
    const float* fc    = (const float*)d_in[1];
    const float* wq_a  = (const float*)d_in[2];
    const float* qnw   = (const float*)d_in[3];
    const float* wq_b  = (const float*)d_in[4];
    const float* wkv_a = (const float*)d_in[5];
    const float* kvnw  = (const float*)d_in[6];
    const float* wkv_b = (const float*)d_in[7];
    const float* wo    = (const float*)d_in[8];
    float* out = (float*)d_out;

    float *cq, *c;
    fp16 *xf, *wqaf, *wqbf, *wkvaf, *wkvbf, *wof, *cqf, *kvnf, *af, *qb, *kb, *vb;
    cudaGetSymbolAddress((void**)&cq,   g_cq);
    cudaGetSymbolAddress((void**)&c,    g_c);
    cudaGetSymbolAddress((void**)&xf,   g_xf);
    cudaGetSymbolAddress((void**)&wqaf, g_wqaf);
    cudaGetSymbolAddress((void**)&wqbf, g_wqbf);
    cudaGetSymbolAddress((void**)&wkvaf,g_wkvaf);
    cudaGetSymbolAddress((void**)&wkvbf,g_wkvbf);
    cudaGetSymbolAddress((void**)&wof,  g_wof);
    cudaGetSymbolAddress((void**)&cqf,  g_cqf);
    cudaGetSymbolAddress((void**)&kvnf, g_kvnf);
    cudaGetSymbolAddress((void**)&af,   g_af);
    cudaGetSymbolAddress((void**)&qb,   g_qb);
    cudaGetSymbolAddress((void**)&kb,   g_kb);
    cudaGetSymbolAddress((void**)&vb,   g_vb);

    const int smem128 = STAGES * (16384 + 128*128); // 131072
    const int smem64  = STAGES * (16384 + 64*128);  // 98304
    cudaFuncSetAttribute(gemm_fp16<128,0>, cudaFuncAttributeMaxDynamicSharedMemorySize, smem128);
    cudaFuncSetAttribute(gemm_fp16<128,1>, cudaFuncAttributeMaxDynamicSharedMemorySize, smem128);
    cudaFuncSetAttribute(gemm_fp16<128,2>, cudaFuncAttributeMaxDynamicSharedMemorySize, smem128);
    cudaFuncSetAttribute(gemm_fp16<64,0>,  cudaFuncAttributeMaxDynamicSharedMemorySize, smem64);
    cudaFuncSetAttribute(attn_mma, cudaFuncAttributeMaxDynamicSharedMemorySize, ATT_SMEM_BYTES);

    // 0) convert operands to fp16
    cvt_pass(x,     xf,   (size_t)ROWS * NDIM);
    cvt_pass(wq_a,  wqaf, (size_t)QRANK * NDIM);
    cvt_pass(wq_b,  wqbf, (size_t)QDIM * QRANK);
    cvt_pass(wkv_a, wkvaf,(size_t)CDIM * NDIM);
    cvt_pass(wkv_b, wkvbf,(size_t)KVDIM * KVRANK);
    cvt_pass(wo,    wof,  (size_t)NDIM * ODIM);

    // 1) cq = x @ wq_a^T  (fp32 out for rmsnorm)
    gemm_fp16<128,0><<<dim3(QRANK/128, ROWS/128), 256, smem128>>>(
        xf, wqaf, cq, nullptr, nullptr, nullptr, ROWS, QRANK, NDIM);
    // 2) rmsnorm(cq) -> fp16
    rmsnorm_cvt_k<<<ROWS, 256>>>(cq, cqf, qnw, QRANK, QRANK);
    // 3) q = cqn @ wq_b^T  (rope + fp16 head-major fused in epilogue)
    gemm_fp16<128,1><<<dim3(QDIM/128, ROWS/128), 256, smem128>>>(
        cqf, wqbf, nullptr, qb, nullptr, fc, ROWS, QDIM, QRANK);
    // 4) c = x @ wkv_a^T  (fp32 out: rmsnorm + k_pe)
    gemm_fp16<64,0><<<dim3(CDIM/64, ROWS/128), 256, smem64>>>(
        xf, wkvaf, c, nullptr, nullptr, nullptr, ROWS, CDIM, NDIM);
    // 5) kvn = rmsnorm(c[:, :512]) -> fp16
    rmsnorm_cvt_k<<<ROWS, 256>>>(c, kvnf, kvnw, KVRANK, CDIM);
    // 5b) k_pe rope -> kb pe columns (all heads)
    kpe_conv_k<<<(NH*ROWS*32 + 255)/256, 256>>>(c, fc, kb);
    // 6) kv = kvn @ wkv_b^T  (fp16 kb/vb scatter fused in epilogue)
    gemm_fp16<128,2><<<dim3(KVDIM/128, ROWS/128), 256, smem128>>>(
        kvnf, wkvbf, nullptr, kb, vb, nullptr, ROWS, KVDIM, KVRANK);
    // 7) tensor-core flash attention -> fp16
    attn_mma<<<dim3(SS/128, NH, BB), 256, ATT_SMEM_BYTES>>>(qb, kb, vb, af);
    // 8) out = attn @ wo^T
    gemm_fp16<128,0><<<dim3(NDIM/128, ROWS/128), 256, smem128>>>(
        af, wof, out, nullptr, nullptr, nullptr, ROWS, NDIM, ODIM);
}

// round 9
// speedup vs baseline: 7.7385x; 1.1028x over previous
#include <cuda_runtime.h>
#include <cuda_bf16.h>
#include <cuda_fp16.h>
#include <math.h>
#include <stdint.h>

// ---------------- problem constants ----------------
#define BB     2
#define SS     2048
#define NDIM   2048
#define NH     16
#define QRANK  1536
#define KVRANK 512
#define ROPE_D 64
#define NOPE_D 128
#define VDIM   128
#define QKH    192           // NOPE + ROPE
#define ROWS   (BB*SS)       // 4096
#define KVDIM  (NH*(NOPE_D+VDIM))  // 4096
#define QDIM   (NH*QKH)      // 3072
#define CDIM   (KVRANK+ROPE_D) // 576
#define ODIM   (NH*VDIM)     // 2048

typedef __half fp16;

// ---------------- scratch (device globals; no allocs allowed) ----------------
__device__ float g_cq [ROWS*QRANK];
__device__ float g_c  [ROWS*CDIM];
// fp16 operand planes
__device__ fp16 g_xf  [ROWS*NDIM];
__device__ fp16 g_wqaf[QRANK*NDIM];
__device__ fp16 g_wqbf[QDIM*QRANK];
__device__ fp16 g_wkvaf[CDIM*NDIM];
__device__ fp16 g_wkvbf[KVDIM*KVRANK];
__device__ fp16 g_wof [NDIM*ODIM];
__device__ fp16 g_cqf [ROWS*QRANK];
__device__ fp16 g_kvnf[ROWS*KVRANK];
__device__ fp16 g_af  [ROWS*ODIM];
// attention operands (head-major layouts)
__device__ fp16 g_qb [NH*ROWS*QKH];     // roped q
__device__ fp16 g_kb [NH*ROWS*QKH];     // k_nope | roped k_pe
__device__ fp16 g_vb [NH*ROWS*VDIM];    // v

// ---------------- helpers ----------------
__device__ __forceinline__ uint32_t packh2(float x, float y) {
    __half2 h = __floats2half2_rn(x, y);
    return *(uint32_t*)&h;
}

// fast exp2 on FMA pipe (x <= 0), rel err ~1e-6
__device__ __forceinline__ float fexp2(float x) {
    x = fmaxf(x, -126.f);
    float fl = floorf(x);
    float f = x - fl;
    float p = 1.535336188319500e-4f;
    p = fmaf(p, f, 1.339887440266574e-3f);
    p = fmaf(p, f, 9.618437357674640e-3f);
    p = fmaf(p, f, 5.550332471162809e-2f);
    p = fmaf(p, f, 2.402264791363012e-1f);
    p = fmaf(p, f, 6.931472028550421e-1f);
    p = fmaf(p, f, 1.0f);
    return p * __int_as_float(((int)fl + 127) << 23);
}

__global__ void cvt_fp16_k(const float4* __restrict__ in, uint2* __restrict__ out, int n4)
{
    int i = blockIdx.x * blockDim.x + threadIdx.x;
    if (i >= n4) return;
    float4 v = in[i];
    uint2 o;
    o.x = packh2(v.x, v.y);
    o.y = packh2(v.z, v.w);
    out[i] = o;
}

__device__ __forceinline__ uint32_t cvta_shared_u32(const void* p) {
    return (uint32_t)__cvta_generic_to_shared(p);
}

#define CP_ASYNC16(dst, src) \
    asm volatile("cp.async.cg.shared.global [%0], [%1], 16;" :: "r"(dst), "l"(src) : "memory")
#define CP_COMMIT() asm volatile("cp.async.commit_group;" ::: "memory")
#define CP_WAIT(N)  asm volatile("cp.async.wait_group %0;" :: "n"(N) : "memory")

#define LDSM_X4(r0,r1,r2,r3,addr) \
    asm volatile("ldmatrix.sync.aligned.m8n8.x4.shared.b16 {%0,%1,%2,%3}, [%4];" \
        : "=r"(r0), "=r"(r1), "=r"(r2), "=r"(r3) : "r"(addr))

#define LDSM_X4T(r0,r1,r2,r3,addr) \
    asm volatile("ldmatrix.sync.aligned.m8n8.x4.trans.shared.b16 {%0,%1,%2,%3}, [%4];" \
        : "=r"(r0), "=r"(r1), "=r"(r2), "=r"(r3) : "r"(addr))

#define MMA_F16(d, a, b) \
    asm volatile("mma.sync.aligned.m16n8k16.row.col.f32.f16.f16.f32 " \
        "{%0,%1,%2,%3}, {%4,%5,%6,%7}, {%8,%9}, {%0,%1,%2,%3};" \
        : "+f"((d)[0]), "+f"((d)[1]), "+f"((d)[2]), "+f"((d)[3]) \
        : "r"((a)[0]), "r"((a)[1]), "r"((a)[2]), "r"((a)[3]), "r"((b)[0]), "r"((b)[1]))

// ---------------- fp16 GEMM: C[M,N] = A[M,K] * B[N,K]^T (fp32 accum) ----------------
// CTA 128 x NT, K-chunk 64 (=128B fp16 row), XOR-8 swizzle, 3-stage cp.async ring,
// 2 CTAs/SM. 8 warps: 2(M) x 4(N), warp tile 64 x NT/4.
// MODE 0: write fp32 C. MODE 1: rope + fp16 head-major qb. MODE 2: fp16 kb/vb scatter.
#define STAGES 3

template<int NT>
__device__ __forceinline__ void load_stage(
    const fp16* __restrict__ A, const fp16* __restrict__ B,
    int K, int m0, int n0, int k0, uint32_t sA, int tid)
{
    constexpr int TOT = (128 + NT) * 8;
    #pragma unroll
    for (int i = 0; i < TOT / 256; i++) {
        int c = tid + i * 256;
        int row = c >> 3;
        int u = c & 7;               // 16B unit within 128B row
        if (row < 128) {
            const fp16* src = A + (size_t)(m0 + row) * K + k0 + u * 8;
            uint32_t dst = sA + row * 128 + ((u ^ (row & 7)) << 4);
            CP_ASYNC16(dst, src);
        } else {
            int br = row - 128;
            const fp16* src = B + (size_t)(n0 + br) * K + k0 + u * 8;
            uint32_t dst = sA + 16384 + br * 128 + ((u ^ (br & 7)) << 4);
            CP_ASYNC16(dst, src);
        }
    }
}

template<int NT, int MODE>
__global__ __launch_bounds__(256, 2) void gemm_fp16(
    const fp16* __restrict__ A, const fp16* __restrict__ B,
    float* __restrict__ C, fp16* __restrict__ O1, fp16* __restrict__ O2,
    const float* __restrict__ fc, int M, int N, int K)
{
    constexpr int WN = NT / 4;
    constexpr int NI = WN / 8;
    constexpr int CHUNK = 16384 + NT * 128;

    extern __shared__ char smem_raw[];
    const uint32_t sbase = cvta_shared_u32(smem_raw);

    const int tid = threadIdx.x;
    const int wid = tid >> 5, lane = tid & 31;
    const int wm = wid >> 2, wn = wid & 3;
    const int m0 = blockIdx.y * 128;
    const int n0 = blockIdx.x * NT;
    const int mat = lane >> 3, r8 = lane & 7;

    float acc[4][NI][4];
    #pragma unroll
    for (int i = 0; i < 4; i++)
        #pragma unroll
        for (int j = 0; j < NI; j++)
            #pragma unroll
            for (int e = 0; e < 4; e++) acc[i][j][e] = 0.f;

    const int kT = K / 64;

    #pragma unroll
    for (int st = 0; st < STAGES - 1; st++) {
        load_stage<NT>(A, B, K, m0, n0, st * 64, sbase + st * CHUNK, tid);
        CP_COMMIT();
    }

    for (int it = 0; it < kT; it++) {
        CP_WAIT(STAGES - 2);
        __syncthreads();

        int nf = it + STAGES - 1;
        if (nf < kT)
            load_stage<NT>(A, B, K, m0, n0, nf * 64,
                           sbase + (nf % STAGES) * CHUNK, tid);
        CP_COMMIT();

        const uint32_t sA = sbase + (it % STAGES) * CHUNK;
        const uint32_t sB = sA + 16384;

        #pragma unroll
        for (int s = 0; s < 4; s++) {          // four k16 steps per 64-chunk
            const int kg = s * 2 + (mat >> 1);
            uint32_t a[4][4];
            uint32_t b[NI][2];

            #pragma unroll
            for (int mt = 0; mt < 4; mt++) {
                int row = wm * 64 + mt * 16 + (mat & 1) * 8 + r8;
                uint32_t rb = sA + row * 128;
                int x7 = row & 7;
                LDSM_X4(a[mt][0], a[mt][1], a[mt][2], a[mt][3],
                        rb + ((kg ^ x7) << 4));
            }
            #pragma unroll
            for (int p = 0; p < NI / 2; p++) {
                int row = wn * WN + p * 16 + (mat & 1) * 8 + r8;
                uint32_t rb = sB + row * 128;
                int x7 = row & 7;
                uint32_t t0, t1, t2, t3;
                LDSM_X4(t0, t1, t2, t3, rb + ((kg ^ x7) << 4));
                b[2*p][0] = t0; b[2*p][1] = t2;
                b[2*p+1][0] = t1; b[2*p+1][1] = t3;
            }

            #pragma unroll
            for (int mt = 0; mt < 4; mt++)
                #pragma unroll
                for (int nt = 0; nt < NI; nt++)
                    MMA_F16(acc[mt][nt], a[mt], b[nt]);
        }
    }

    const int qm = lane >> 2, qn = (lane & 3) * 2;
    #pragma unroll
    for (int mt = 0; mt < 4; mt++)
        #pragma unroll
        for (int nt = 0; nt < NI; nt++) {
            int m = m0 + wm * 64 + mt * 16 + qm;     // rows m, m+8
            int n = n0 + wn * WN + nt * 8 + qn;      // cols n, n+1 (n even)
            float v0 = acc[mt][nt][0], v1 = acc[mt][nt][1];
            float v2 = acc[mt][nt][2], v3 = acc[mt][nt][3];
            if (MODE == 0) {
                *(float2*)&C[(size_t)m * N + n]       = make_float2(v0, v1);
                *(float2*)&C[(size_t)(m + 8) * N + n] = make_float2(v2, v3);
            } else if (MODE == 1) {
                // q: rope on pe pairs, fp16 head-major
                int h = n / QKH, p2 = n % QKH;
                if (p2 >= NOPE_D) {
                    int pp = (p2 - NOPE_D) >> 1;
                    int s0 = m & (SS - 1), s8 = (m + 8) & (SS - 1);
                    float cs0 = fc[(s0 * 32 + pp) * 2], sn0 = fc[(s0 * 32 + pp) * 2 + 1];
                    float cs8 = fc[(s8 * 32 + pp) * 2], sn8 = fc[(s8 * 32 + pp) * 2 + 1];
                    float r0 = v0 * cs0 - v1 * sn0, i0 = v0 * sn0 + v1 * cs0;
                    float r2 = v2 * cs8 - v3 * sn8, i2 = v2 * sn8 + v3 * cs8;
                    v0 = r0; v1 = i0; v2 = r2; v3 = i2;
                }
                fp16* dst = O1 + ((size_t)h * ROWS + m) * QKH + p2;
                *(uint32_t*)dst               = packh2(v0, v1);
                *(uint32_t*)(dst + 8 * QKH)   = packh2(v2, v3);
            } else {
                // kv: scatter k_nope -> O1 (kb), v -> O2 (vb)
                int h = n >> 8, c2 = n & 255;
                if (c2 < NOPE_D) {
                    fp16* dst = O1 + ((size_t)h * ROWS + m) * QKH + c2;
                    *(uint32_t*)dst             = packh2(v0, v1);
                    *(uint32_t*)(dst + 8 * QKH) = packh2(v2, v3);
                } else {
                    fp16* dst = O2 + ((size_t)h * ROWS + m) * VDIM + (c2 - NOPE_D);
                    *(uint32_t*)dst              = packh2(v0, v1);
                    *(uint32_t*)(dst + 8 * VDIM) = packh2(v2, v3);
                }
            }
        }
}

// ---------------- RMSNorm -> fp16 plane ----------------
__global__ __launch_bounds__(256) void rmsnorm_cvt_k(
    const float* __restrict__ in, fp16* __restrict__ o,
    const float* __restrict__ w, int L, int sin)
{
    __shared__ float red[8];
    const int row = blockIdx.x;
    const float* ip = in + (size_t)row * sin;
    float ss = 0.f;
    for (int i = threadIdx.x; i < L; i += 256) {
        float v = ip[i];
        ss = fmaf(v, v, ss);
    }
    #pragma unroll
    for (int off = 16; off; off >>= 1)
        ss += __shfl_xor_sync(0xffffffffu, ss, off);
    if ((threadIdx.x & 31) == 0) red[threadIdx.x >> 5] = ss;
    __syncthreads();
    if (threadIdx.x == 0) {
        float tot = 0.f;
        #pragma unroll
        for (int i = 0; i < 8; i++) tot += red[i];
        red[0] = rsqrtf(tot / (float)L + 1e-6f);
    }
    __syncthreads();
    float inv = red[0];
    for (int i = threadIdx.x; i < L; i += 256)
        o[(size_t)row * L + i] = __float2half_rn(ip[i] * inv * w[i]);
}

// ---------------- k_pe conversion (rope; shared across heads) ----------------
__global__ void kpe_conv_k(const float* __restrict__ c, const float* __restrict__ fc,
                           fp16* __restrict__ kb)
{
    int idx = blockIdx.x * blockDim.x + threadIdx.x;
    if (idx >= NH * ROWS * 32) return;
    int p = idx & 31;
    int rowh = idx >> 5;
    int row = rowh & (ROWS - 1);
    int h = rowh >> 12;
    int s = row & (SS - 1);
    const float* src = c + (size_t)row * CDIM + KVRANK + 2 * p;
    float a = src[0], b = src[1];
    float cs = fc[(s * 32 + p) * 2 + 0];
    float sn = fc[(s * 32 + p) * 2 + 1];
    float v0 = a * cs - b * sn;
    float v1 = a * sn + b * cs;
    *(uint32_t*)(kb + ((size_t)h * ROWS + row) * QKH + NOPE_D + 2 * p) = packh2(v0, v1);
}

// ---------------- tensor-core flash attention (fp16) ----------------
// q-tile 128 rows, 8 warps x m16; key tiles 64; D=192.
// smem (fp16 elems): Q 128x200, K[2] 64x200, V[2] 64x136.
#define ATT_SMEM_BYTES ((128*200 + 2*64*200 + 2*64*136) * 2)

__global__ __launch_bounds__(256, 1) void attn_mma(
    const fp16* __restrict__ gq, const fp16* __restrict__ gk,
    const fp16* __restrict__ gv, fp16* __restrict__ go)
{
    extern __shared__ fp16 asm_[];
    const uint32_t sQ = cvta_shared_u32(asm_);
    const uint32_t sK = sQ + 128 * 200 * 2;
    const uint32_t sV = sK + 2 * 64 * 200 * 2;

    const int tid = threadIdx.x;
    const int wid = tid >> 5, lane = tid & 31;
    const int qt = gridDim.x - 1 - blockIdx.x;
    const int q0 = qt * 128;
    const int h  = blockIdx.y;
    const int b  = blockIdx.z;
    const size_t hb = (size_t)h * ROWS + b * SS;

    {
        const fp16* qbase = gq + (hb + q0) * QKH;
        for (int i = tid; i < 3072; i += 256) {
            int row = i / 24, u = i - row * 24;
            CP_ASYNC16(sQ + (row * 200 + u * 8) * 2, qbase + row * QKH + u * 8);
        }
    }

    const int nT = q0 / 64 + 2;

    auto load_tile = [&](int n0, int buf) {
        const fp16* kbase = gk + (hb + n0) * QKH;
        uint32_t kd = sK + buf * (64 * 200 * 2);
        for (int i = tid; i < 1536; i += 256) {
            int row = i / 24, u = i - row * 24;
            CP_ASYNC16(kd + (row * 200 + u * 8) * 2, kbase + row * QKH + u * 8);
        }
        const fp16* vbase = gv + (hb + n0) * VDIM;
        uint32_t vd = sV + buf * (64 * 136 * 2);
        for (int i = tid; i < 1024; i += 256) {
            int row = i >> 4, u = i & 15;
            CP_ASYNC16(vd + (row * 136 + u * 8) * 2, vbase + row * VDIM + u * 8);
        }
    };

    load_tile(0, 0);
    CP_COMMIT();

    float out[16][4];
    #pragma unroll
    for (int f = 0; f < 16; f++)
        #pragma unroll
        for (int e = 0; e < 4; e++) out[f][e] = 0.f;
    float m0 = -1e30f, m1 = -1e30f, l0 = 0.f, l1 = 0.f;

    const int mat = lane >> 3, r8 = lane & 7;
    const uint32_t aQ = sQ + ((wid * 16 + (lane & 15)) * 200 + (lane >> 4) * 8) * 2;
    const float sc2 = 0.07216878364870323f * 1.4426950408889634f;
    const int growA = q0 + wid * 16 + (lane >> 2);

    for (int t = 0; t < nT; t++) {
        const int buf = t & 1;
        if (t + 1 < nT) load_tile(64 * (t + 1), buf ^ 1);
        CP_COMMIT();
        CP_WAIT(1);
        __syncthreads();

        const int n0 = 64 * t;
        const bool active = (n0 <= q0 + wid * 16 + 15);
        if (active) {
            // ---- S = Q @ K^T ----
            float s[8][4];
            #pragma unroll
            for (int f = 0; f < 8; f++)
                #pragma unroll
                for (int e = 0; e < 4; e++) s[f][e] = 0.f;

            const uint32_t kB = sK + buf * (64 * 200 * 2)
                              + (((mat >> 1) * 8 + r8) * 200 + (mat & 1) * 8) * 2;
            #pragma unroll
            for (int kt = 0; kt < 12; kt++) {
                uint32_t a[4];
                LDSM_X4(a[0], a[1], a[2], a[3], aQ + kt * 32);
                #pragma unroll
                for (int g = 0; g < 4; g++) {
                    uint32_t b0, b1, b2, b3;
                    LDSM_X4(b0, b1, b2, b3, kB + (g * 16 * 200) * 2 + kt * 32);
                    uint32_t bb0[2] = {b0, b1}, bb1[2] = {b2, b3};
                    MMA_F16(s[2*g],   a, bb0);
                    MMA_F16(s[2*g+1], a, bb1);
                }
            }

            // ---- online softmax (log2 domain) ----
            const bool needmask = (n0 + 63 > q0 + wid * 16);
            const int colb = n0 + 2 * (lane & 3);
            float rm0 = -1e30f, rm1 = -1e30f;
            #pragma unroll
            for (int f = 0; f < 8; f++) {
                #pragma unroll
                for (int j = 0; j < 2; j++) {
                    int col = colb + f * 8 + j;
                    float z0 = s[f][j]     * sc2;
                    float z1 = s[f][2 + j] * sc2;
                    if (needmask) {
                        if (col > growA)     z0 = -1e30f;
                        if (col > growA + 8) z1 = -1e30f;
                    }
                    s[f][j] = z0; s[f][2 + j] = z1;
                    rm0 = fmaxf(rm0, z0); rm1 = fmaxf(rm1, z1);
                }
            }
            rm0 = fmaxf(rm0, __shfl_xor_sync(0xffffffffu, rm0, 1));
            rm0 = fmaxf(rm0, __shfl_xor_sync(0xffffffffu, rm0, 2));
            rm1 = fmaxf(rm1, __shfl_xor_sync(0xffffffffu, rm1, 1));
            rm1 = fmaxf(rm1, __shfl_xor_sync(0xffffffffu, rm1, 2));
            float mn0 = fmaxf(m0, rm0), mn1 = fmaxf(m1, rm1);
            float al0 = fexp2(m0 - mn0), al1 = fexp2(m1 - mn1);
            m0 = mn0; m1 = mn1;

            float rs0 = 0.f, rs1 = 0.f;
            #pragma unroll
            for (int f = 0; f < 8; f++) {
                #pragma unroll
                for (int j = 0; j < 2; j++) {
                    float p0 = fexp2(s[f][j]     - mn0);
                    float p1 = fexp2(s[f][2 + j] - mn1);
                    s[f][j] = p0; s[f][2 + j] = p1;
                    rs0 += p0; rs1 += p1;
                }
            }
            rs0 += __shfl_xor_sync(0xffffffffu, rs0, 1);
            rs0 += __shfl_xor_sync(0xffffffffu, rs0, 2);
            rs1 += __shfl_xor_sync(0xffffffffu, rs1, 1);
            rs1 += __shfl_xor_sync(0xffffffffu, rs1, 2);
            l0 = l0 * al0 + rs0;
            l1 = l1 * al1 + rs1;

            #pragma unroll
            for (int f = 0; f < 16; f++) {
                out[f][0] *= al0; out[f][1] *= al0;
                out[f][2] *= al1; out[f][3] *= al1;
            }

            // ---- O += P @ V (fp16) ----
            const uint32_t vB = sV + buf * (64 * 136 * 2)
                              + (((mat & 1) * 8 + r8) * 136 + (mat >> 1) * 8) * 2;
            #pragma unroll
            for (int kt = 0; kt < 4; kt++) {
                uint32_t pa[4];
                pa[0] = packh2(s[2*kt][0],   s[2*kt][1]);
                pa[1] = packh2(s[2*kt][2],   s[2*kt][3]);
                pa[2] = packh2(s[2*kt+1][0], s[2*kt+1][1]);
                pa[3] = packh2(s[2*kt+1][2], s[2*kt+1][3]);
                const uint32_t rowOff = (kt * 16 * 136) * 2;
                #pragma unroll
                for (int gv = 0; gv < 8; gv++) {
                    uint32_t h0, h1, h2, h3;
                    LDSM_X4T(h0, h1, h2, h3, vB + rowOff + gv * 32);
                    uint32_t bh0[2] = {h0, h1}, bh1[2] = {h2, h3};
                    MMA_F16(out[2*gv],   pa, bh0);
                    MMA_F16(out[2*gv+1], pa, bh1);
                }
            }
        }
        __syncthreads();
    }

    // ---- finalize ----
    float inv0 = 1.f / l0, inv1 = 1.f / l1;
    size_t r0g = (size_t)(b * SS + q0 + wid * 16 + (lane >> 2));
    size_t base0 = r0g * ODIM + h * VDIM + 2 * (lane & 3);
    size_t base1 = base0 + 8 * (size_t)ODIM;
    #pragma unroll
    for (int f = 0; f < 16; f++) {
        *(uint32_t*)&go[base0 + f * 8] = packh2(out[f][0] * inv0, out[f][1] * inv0);
        *(uint32_t*)&go[base1 + f * 8] = packh2(out[f][2] * inv1, out[f][3] * inv1);
    }
}

// ---------------- launcher ----------------
static inline void cvt_pass_s(const float* src, fp16* dst, size_t n, cudaStream_t st)
{
    int n4 = (int)(n / 4);
    cvt_fp16_k<<<(n4 + 255) / 256, 256, 0, st>>>((const float4*)src, (uint2*)dst, n4);
}

extern "C" void kernel_launch(void* const* d_in, const int* in_sizes, int n_in,
                              void* d_out, int out_size)
{
    const float* x     = (const float*)d_in[0];
    const float* fc    = (const float*)d_in[1];
    const float* wq_a  = (const float*)d_in[2];
    const float* qnw   = (const float*)d_in[3];
    const float* wq_b  = (const float*)d_in[4];
    const float* wkv_a = (const float*)d_in[5];
    const float* kvnw  = (const float*)d_in[6];
    const float* wkv_b = (const float*)d_in[7];
    const float* wo    = (const float*)d_in[8];
    float* out = (float*)d_out;

    float *cq, *c;
    fp16 *xf, *wqaf, *wqbf, *wkvaf, *wkvbf, *wof, *cqf, *kvnf, *af, *qb, *kb, *vb;
    cudaGetSymbolAddress((void**)&cq,   g_cq);
    cudaGetSymbolAddress((void**)&c,    g_c);
    cudaGetSymbolAddress((void**)&xf,   g_xf);
    cudaGetSymbolAddress((void**)&wqaf, g_wqaf);
    cudaGetSymbolAddress((void**)&wqbf, g_wqbf);
    cudaGetSymbolAddress((void**)&wkvaf,g_wkvaf);
    cudaGetSymbolAddress((void**)&wkvbf,g_wkvbf);
    cudaGetSymbolAddress((void**)&wof,  g_wof);
    cudaGetSymbolAddress((void**)&cqf,  g_cqf);
    cudaGetSymbolAddress((void**)&kvnf, g_kvnf);
    cudaGetSymbolAddress((void**)&af,   g_af);
    cudaGetSymbolAddress((void**)&qb,   g_qb);
    cudaGetSymbolAddress((void**)&kb,   g_kb);
    cudaGetSymbolAddress((void**)&vb,   g_vb);

    // one-time side-stream/event creation (host resources; identical launch
    // graph every call, so capture sees the same nodes each time)
    static cudaStream_t s1 = nullptr;
    static cudaEvent_t eFork = nullptr, eJoin = nullptr;
    if (s1 == nullptr) {
        cudaStreamCreateWithFlags(&s1, cudaStreamNonBlocking);
        cudaEventCreateWithFlags(&eFork, cudaEventDisableTiming);
        cudaEventCreateWithFlags(&eJoin, cudaEventDisableTiming);
    }
    cudaStream_t s0 = 0;  // capture/default stream

    const int smem128 = STAGES * (16384 + 128*128); // 98304
    const int smem64  = STAGES * (16384 + 64*128);  // 73728
    cudaFuncSetAttribute(gemm_fp16<128,0>, cudaFuncAttributeMaxDynamicSharedMemorySize, smem128);
    cudaFuncSetAttribute(gemm_fp16<128,1>, cudaFuncAttributeMaxDynamicSharedMemorySize, smem128);
    cudaFuncSetAttribute(gemm_fp16<128,2>, cudaFuncAttributeMaxDynamicSharedMemorySize, smem128);
    cudaFuncSetAttribute(gemm_fp16<64,0>,  cudaFuncAttributeMaxDynamicSharedMemorySize, smem64);
    cudaFuncSetAttribute(attn_mma, cudaFuncAttributeMaxDynamicSharedMemorySize, ATT_SMEM_BYTES);

    // ---- s0: x + q-branch weights; fork point after xf is ready ----
    cvt_pass_s(x,    xf,   (size_t)ROWS * NDIM, s0);
    cudaEventRecord(eFork, s0);                 // xf ready -> kv branch may start
    cvt_pass_s(wq_a, wqaf, (size_t)QRANK * NDIM, s0);
    cvt_pass_s(wq_b, wqbf, (size_t)QDIM * QRANK, s0);
    cvt_pass_s(wo,   wof,  (size_t)NDIM * ODIM, s0);

    // ---- s1 (kv branch): wkv weights, GEMM4 -> rmsnorm -> kpe -> GEMM6 ----
    cudaStreamWaitEvent(s1, eFork, 0);
    cvt_pass_s(wkv_a, wkvaf, (size_t)CDIM * NDIM, s1);
    cvt_pass_s(wkv_b, wkvbf, (size_t)KVDIM * KVRANK, s1);
    gemm_fp16<64,0><<<dim3(CDIM/64, ROWS/128), 256, smem64, s1>>>(
        xf, wkvaf, c, nullptr, nullptr, nullptr, ROWS, CDIM, NDIM);
    rmsnorm_cvt_k<<<ROWS, 256, 0, s1>>>(c, kvnf, kvnw, KVRANK, CDIM);
    kpe_conv_k<<<(NH*ROWS*32 + 255)/256, 256, 0, s1>>>(c, fc, kb);
    gemm_fp16<128,2><<<dim3(KVDIM/128, ROWS/128), 256, smem128, s1>>>(
        kvnf, wkvbf, nullptr, kb, vb, nullptr, ROWS, KVDIM, KVRANK);
    cudaEventRecord(eJoin, s1);

    // ---- s0 (q branch): GEMM1 -> rmsnorm -> GEMM3 ----
    gemm_fp16<128,0><<<dim3(QRANK/128, ROWS/128), 256, smem128, s0>>>(
        xf, wqaf, cq, nullptr, nullptr, nullptr, ROWS, QRANK, NDIM);
    rmsnorm_cvt_k<<<ROWS, 256, 0, s0>>>(cq, cqf, qnw, QRANK, QRANK);
    gemm_fp16<128,1><<<dim3(QDIM/128, ROWS/128), 256, smem128, s0>>>(
        cqf, wqbf, nullptr, qb, nullptr, fc, ROWS, QDIM, QRANK);

    // ---- join, attention, output GEMM ----
    cudaStreamWaitEvent(s0, eJoin, 0);
    attn_mma<<<dim3(SS/128, NH, BB), 256, ATT_SMEM_BYTES, s0>>>(qb, kb, vb, af);
    gemm_fp16<128,0><<<dim3(NDIM/128, ROWS/128), 256, smem128, s0>>>(
        af, wof, out, nullptr, nullptr, nullptr, ROWS, NDIM, ODIM);
}